// round 14
// baseline (speedup 1.0000x reference)
#include <cuda_runtime.h>
#include <cuda_bf16.h>
#include <math.h>
#include <stdint.h>

#define EPSF 1e-5f
#define SCALEF 0.17677669529663687f

#define NB   64
#define NPIX 196
#define DHC  1024
#define NCOL 12544   // 64*196
#define KPAD 208     // padded k (m) dimension for AV mma (13*16)

// ------------------------------------------------------------------
// scratch (no cudaMalloc allowed)
__device__ float g_vloc[NB * DHC * NPIX];    // [b][1024][196]
__device__ float g_logits[512 * 196 * 196];  // [(b*8+h)][n][m] post-bias logits

__device__ __align__(16) __nv_bfloat16 g_xt_hi[NCOL * 384];   // [j][k]
__device__ __align__(16) __nv_bfloat16 g_xt_lo[NCOL * 384];
__device__ __align__(16) __nv_bfloat16 g_pt_hi[NCOL * 1024];  // [j][k]
__device__ __align__(16) __nv_bfloat16 g_pt_lo[NCOL * 1024];
__device__ __align__(16) __nv_bfloat16 g_wqkv_hi[1536 * 384]; // [m][k]
__device__ __align__(16) __nv_bfloat16 g_wqkv_lo[1536 * 384];
__device__ __align__(16) __nv_bfloat16 g_wp_hi[384 * 1024];
__device__ __align__(16) __nv_bfloat16 g_wp_lo[384 * 1024];
// q/k export: [(b*16 + hh)][n][d=32] bf16 hi/lo; hh 0-7 = q heads, 8-15 = k heads
__device__ __align__(16) __nv_bfloat16 g_qkh_hi[NB * 16 * 196 * 32];
__device__ __align__(16) __nv_bfloat16 g_qkh_lo[NB * 16 * 196 * 32];
// attention P (post-softmax/TH2) bf16 hi/lo: [(b*8+o)*196 + n][k=KPAD] (+ tail pad)
__device__ __align__(16) __nv_bfloat16 g_phi[512 * 196 * KPAD + 128];
__device__ __align__(16) __nv_bfloat16 g_plo[512 * 196 * KPAD + 128];
// BN'd V bf16 hi/lo: [b][c(1024)][k=KPAD] (written by qkv GEMM epilogue)
__device__ __align__(16) __nv_bfloat16 g_vhi[NB * 1024 * KPAD + 128];
__device__ __align__(16) __nv_bfloat16 g_vlo[NB * 1024 * KPAD + 128];
__device__ float g_s[1920];   // folded BN scale: [0:1536) qkv, [1536:1920) proj
__device__ float g_t[1920];   // folded BN shift

// ------------------------------------------------------------------
static __device__ __forceinline__ uint32_t s2u(const void* p) {
    uint32_t a;
    asm("{ .reg .u64 t; cvta.to.shared.u64 t, %1; cvt.u32.u64 %0, t; }"
        : "=r"(a) : "l"(p));
    return a;
}

static __device__ __forceinline__ void cp_async16(uint32_t saddr, const void* gptr) {
    asm volatile("cp.async.cg.shared.global [%0], [%1], 16;"
                 :: "r"(saddr), "l"(gptr) : "memory");
}

static __device__ __forceinline__ void cp_async16_zf(uint32_t saddr, const void* gptr, int valid) {
    int sz = valid ? 16 : 0;
    asm volatile("cp.async.cg.shared.global [%0], [%1], 16, %2;"
                 :: "r"(saddr), "l"(gptr), "r"(sz) : "memory");
}

static __device__ __forceinline__ void ldmat_x4(
    uint32_t& r0, uint32_t& r1, uint32_t& r2, uint32_t& r3, uint32_t addr)
{
    asm volatile("ldmatrix.sync.aligned.m8n8.x4.shared.b16 {%0,%1,%2,%3}, [%4];"
                 : "=r"(r0), "=r"(r1), "=r"(r2), "=r"(r3) : "r"(addr));
}

static __device__ __forceinline__ void mma_bf16(
    float& d0, float& d1, float& d2, float& d3,
    uint32_t a0, uint32_t a1, uint32_t a2, uint32_t a3,
    uint32_t b0, uint32_t b1)
{
    asm volatile(
        "mma.sync.aligned.m16n8k16.row.col.f32.bf16.bf16.f32 "
        "{%0,%1,%2,%3}, {%4,%5,%6,%7}, {%8,%9}, {%0,%1,%2,%3};"
        : "+f"(d0), "+f"(d1), "+f"(d2), "+f"(d3)
        : "r"(a0), "r"(a1), "r"(a2), "r"(a3), "r"(b0), "r"(b1));
}

// ------------------------------------------------------------------
// Prep 1 (critical path): fold BN scale/shift; split qkv weights bf16 hi/lo.
__global__ void __launch_bounds__(256) prep_kernel(
    const float* __restrict__ wq, const float* __restrict__ wk,
    const float* __restrict__ wv,
    const float* __restrict__ bq, const float* __restrict__ bk,
    const float* __restrict__ bv, const float* __restrict__ bp,
    const float* __restrict__ bnq, const float* __restrict__ bnk,
    const float* __restrict__ bnv, const float* __restrict__ bnp)
{
    int idx = blockIdx.x * 256 + threadIdx.x;
    int stride = gridDim.x * 256;

    for (int i = idx; i < 1536 * 384; i += stride) {
        int m = i / 384;
        float w = (m < 256) ? wq[i]
                : (m < 512) ? wk[i - 256 * 384]
                            : wv[i - 512 * 384];
        __nv_bfloat16 h = __float2bfloat16(w);
        g_wqkv_hi[i] = h;
        g_wqkv_lo[i] = __float2bfloat16(w - __bfloat162float(h));
    }
    if (idx < 1920) {
        const float* bn; const float* bias; int c; int C;
        if (idx < 256)       { bn = bnq; bias = bq; c = idx;        C = 256; }
        else if (idx < 512)  { bn = bnk; bias = bk; c = idx - 256;  C = 256; }
        else if (idx < 1536) { bn = bnv; bias = bv; c = idx - 512;  C = 1024; }
        else                 { bn = bnp; bias = bp; c = idx - 1536; C = 384; }
        float s = bn[c] * rsqrtf(bn[3 * C + c] + EPSF);
        g_s[idx] = s;
        g_t[idx] = (bias[c] - bn[2 * C + c]) * s + bn[C + c];
    }
}

// Prep 2 (off critical path; overlaps qkv GEMM): wp split + all pad zeroing.
__global__ void __launch_bounds__(256) prep2_kernel(const float* __restrict__ wp)
{
    int idx = blockIdx.x * 256 + threadIdx.x;
    int stride = gridDim.x * 256;

    for (int i = idx; i < 384 * 1024; i += stride) {
        float w = wp[i];
        __nv_bfloat16 h = __float2bfloat16(w);
        g_wp_hi[i] = h;
        g_wp_lo[i] = __float2bfloat16(w - __bfloat162float(h));
    }
    for (long i = idx; i < (long)100352 * 3; i += stride) {
        long r = i / 3; int k = (int)(i % 3);
        *(unsigned long long*)((char*)g_phi + r * 416 + 392 + k * 8) = 0ull;
        *(unsigned long long*)((char*)g_plo + r * 416 + 392 + k * 8) = 0ull;
    }
    for (long i = idx; i < (long)65536 * 3; i += stride) {
        long r = i / 3; int k = (int)(i % 3);
        *(unsigned long long*)((char*)g_vhi + r * 416 + 392 + k * 8) = 0ull;
        *(unsigned long long*)((char*)g_vlo + r * 416 + 392 + k * 8) = 0ull;
    }
    if (idx < 128) {
        g_phi[512 * 196 * KPAD + idx] = __float2bfloat16(0.f);
        g_plo[512 * 196 * KPAD + idx] = __float2bfloat16(0.f);
        g_vhi[NB * 1024 * KPAD + idx] = __float2bfloat16(0.f);
        g_vlo[NB * 1024 * KPAD + idx] = __float2bfloat16(0.f);
    }
}

// ------------------------------------------------------------------
// Transpose+split x: [b][384][196] -> Xt[j=b*196+n][k=c] bf16 hi/lo
__global__ void __launch_bounds__(256) xt_cvt_kernel(const float* __restrict__ X)
{
    __shared__ float t[32][29];
    int b = blockIdx.z, c0 = blockIdx.y * 32, n0 = blockIdx.x * 28;
    int tid = threadIdx.x;
    const float* src = X + ((size_t)b * 384 + c0) * 196 + n0;
    for (int i = tid; i < 32 * 28; i += 256) {
        int ci = i / 28, nj = i - ci * 28;
        t[ci][nj] = src[(size_t)ci * 196 + nj];
    }
    __syncthreads();
    for (int i = tid; i < 32 * 28; i += 256) {
        int nj = i >> 5, ci = i & 31;
        float v = t[ci][nj];
        __nv_bfloat16 h = __float2bfloat16(v);
        size_t o = ((size_t)(b * 196 + n0 + nj)) * 384 + c0 + ci;
        g_xt_hi[o] = h;
        g_xt_lo[o] = __float2bfloat16(v - __bfloat162float(h));
    }
}

// ------------------------------------------------------------------
// bf16 mma.sync GEMM v3: 128x128 tile, K-chunk 32, 3-stage cp.async,
// 2 blocks/SM (reg cap 128). SW64 swizzle (64B rows).
// smem/stage: Ahi 8K | Alo 8K | Bhi 8K | Blo 8K = 32K; 3 stages = 96K.
#define GEMM_STAGE_BYTES 32768
#define GEMM_SMEM_BYTES  (3 * GEMM_STAGE_BYTES)

__global__ void __launch_bounds__(256, 2) gemm_mma_kernel(
    const __nv_bfloat16* __restrict__ Ahi, const __nv_bfloat16* __restrict__ Alo,
    const __nv_bfloat16* __restrict__ Bhi, const __nv_bfloat16* __restrict__ Blo,
    int K, const float* __restrict__ svec, const float* __restrict__ tvec,
    float* __restrict__ out, int Cout,
    __nv_bfloat16* __restrict__ qk_hi, __nv_bfloat16* __restrict__ qk_lo)
{
    extern __shared__ __align__(1024) char smem[];
    const uint32_t sb = s2u(smem);
    const int tid = threadIdx.x;
    const int wid = tid >> 5, lane = tid & 31;
    const int warp_m = wid & 1;
    const int warp_n = wid >> 1;
    const int m0 = blockIdx.y * 128;
    const int j0 = blockIdx.x * 128;
    const int nk = K >> 5;             // 32-wide k-chunks
    const bool is_qkv = (qk_hi != nullptr);

    float acc[4][4][4];
#pragma unroll
    for (int i = 0; i < 4; i++)
#pragma unroll
        for (int j = 0; j < 4; j++)
#pragma unroll
            for (int c = 0; c < 4; c++) acc[i][j][c] = 0.f;

    const int lrow = lane & 15;
    const uint32_t lkoff = (uint32_t)((lane >> 4) << 4);

    auto issue = [&](int ch, uint32_t stage_off) {
        int kb = ch << 5;
#pragma unroll
        for (int i = 0; i < 2; i++) {
            int q = tid + (i << 8);
            int row = q >> 2, k8 = q & 3;
            uint32_t off = (uint32_t)(row * 64 + k8 * 16);
            uint32_t sw = off ^ ((off >> 3) & 0x30);
            size_t ga = (size_t)(m0 + row) * K + kb + (k8 << 3);
            size_t gb = (size_t)(j0 + row) * K + kb + (k8 << 3);
            cp_async16(sb + stage_off + sw,           Ahi + ga);
            cp_async16(sb + stage_off + 8192u + sw,   Alo + ga);
            cp_async16(sb + stage_off + 16384u + sw,  Bhi + gb);
            cp_async16(sb + stage_off + 24576u + sw,  Blo + gb);
        }
        asm volatile("cp.async.commit_group;" ::: "memory");
    };

    issue(0, 0u);
    if (nk > 1) issue(1, GEMM_STAGE_BYTES);
    if (nk > 2) issue(2, 2u * GEMM_STAGE_BYTES);

    for (int ch = 0; ch < nk; ch++) {
        if (ch + 2 < nk)      asm volatile("cp.async.wait_group 2;" ::: "memory");
        else if (ch + 1 < nk) asm volatile("cp.async.wait_group 1;" ::: "memory");
        else                  asm volatile("cp.async.wait_group 0;" ::: "memory");
        __syncthreads();

        const uint32_t buf = (uint32_t)(ch % 3) * GEMM_STAGE_BYTES;
#pragma unroll
        for (int ks = 0; ks < 2; ks++) {
            uint32_t bh[4][2], bl[4][2];
#pragma unroll
            for (int p = 0; p < 2; p++) {
                uint32_t off = (uint32_t)((warp_n * 32 + p * 16 + lrow) * 64)
                             + (uint32_t)(ks * 32) + lkoff;
                uint32_t sw = off ^ ((off >> 3) & 0x30);
                uint32_t r0, r1, r2, r3;
                ldmat_x4(r0, r1, r2, r3, sb + buf + 16384u + sw);
                bh[p * 2 + 0][0] = r0; bh[p * 2 + 1][0] = r1;
                bh[p * 2 + 0][1] = r2; bh[p * 2 + 1][1] = r3;
                ldmat_x4(r0, r1, r2, r3, sb + buf + 24576u + sw);
                bl[p * 2 + 0][0] = r0; bl[p * 2 + 1][0] = r1;
                bl[p * 2 + 0][1] = r2; bl[p * 2 + 1][1] = r3;
            }
#pragma unroll
            for (int mt = 0; mt < 4; mt++) {
                uint32_t off = (uint32_t)((warp_m * 64 + mt * 16 + lrow) * 64)
                             + (uint32_t)(ks * 32) + lkoff;
                uint32_t sw = off ^ ((off >> 3) & 0x30);
                uint32_t a0, a1, a2, a3;
                ldmat_x4(a0, a1, a2, a3, sb + buf + sw);
#pragma unroll
                for (int nt = 0; nt < 4; nt++)
                    mma_bf16(acc[mt][nt][0], acc[mt][nt][1],
                             acc[mt][nt][2], acc[mt][nt][3],
                             a0, a1, a2, a3, bh[nt][0], bh[nt][1]);
#pragma unroll
                for (int nt = 0; nt < 4; nt++)
                    mma_bf16(acc[mt][nt][0], acc[mt][nt][1],
                             acc[mt][nt][2], acc[mt][nt][3],
                             a0, a1, a2, a3, bl[nt][0], bl[nt][1]);
                ldmat_x4(a0, a1, a2, a3, sb + buf + 8192u + sw);
#pragma unroll
                for (int nt = 0; nt < 4; nt++)
                    mma_bf16(acc[mt][nt][0], acc[mt][nt][1],
                             acc[mt][nt][2], acc[mt][nt][3],
                             a0, a1, a2, a3, bh[nt][0], bh[nt][1]);
            }
        }

        if (ch + 3 < nk) {
            __syncthreads();
            issue(ch + 3, buf);
        }
    }

    const int group = lane >> 2, tig = lane & 3;
#pragma unroll
    for (int mt = 0; mt < 4; mt++) {
        int oc0 = m0 + warp_m * 64 + mt * 16 + group;
        int oc1 = oc0 + 8;
        float s0 = svec[oc0], t0 = tvec[oc0];
        float s1 = svec[oc1], t1 = tvec[oc1];
#pragma unroll
        for (int nt = 0; nt < 4; nt++) {
            int j = j0 + warp_n * 32 + nt * 8 + tig * 2;
            int b = j / 196, n = j - b * 196;
            float v00 = acc[mt][nt][0] * s0 + t0;
            float v01 = acc[mt][nt][1] * s0 + t0;
            float v10 = acc[mt][nt][2] * s1 + t1;
            float v11 = acc[mt][nt][3] * s1 + t1;
            if (!is_qkv) {
                float* p0 = out + ((size_t)b * Cout + oc0) * 196 + n;
                float* p1 = out + ((size_t)b * Cout + oc1) * 196 + n;
                p0[0] = v00; p0[1] = v01;
                p1[0] = v10; p1[1] = v11;
            } else if (m0 < 512) {
                size_t r0 = (((size_t)(b * 16) + (oc0 >> 5)) * 196 + n) * 32 + (oc0 & 31);
                size_t r1 = (((size_t)(b * 16) + (oc1 >> 5)) * 196 + n) * 32 + (oc1 & 31);
                __nv_bfloat16 h;
                h = __float2bfloat16(v00); qk_hi[r0] = h;
                qk_lo[r0] = __float2bfloat16(v00 - __bfloat162float(h));
                h = __float2bfloat16(v01); qk_hi[r0 + 32] = h;
                qk_lo[r0 + 32] = __float2bfloat16(v01 - __bfloat162float(h));
                h = __float2bfloat16(v10); qk_hi[r1] = h;
                qk_lo[r1] = __float2bfloat16(v10 - __bfloat162float(h));
                h = __float2bfloat16(v11); qk_hi[r1 + 32] = h;
                qk_lo[r1 + 32] = __float2bfloat16(v11 - __bfloat162float(h));
            } else {
                size_t r0 = ((size_t)b * 1024 + (oc0 - 512)) * KPAD + n;
                size_t r1 = ((size_t)b * 1024 + (oc1 - 512)) * KPAD + n;
                __nv_bfloat16 h;
                h = __float2bfloat16(v00); g_vhi[r0] = h;
                g_vlo[r0] = __float2bfloat16(v00 - __bfloat162float(h));
                h = __float2bfloat16(v01); g_vhi[r0 + 1] = h;
                g_vlo[r0 + 1] = __float2bfloat16(v01 - __bfloat162float(h));
                h = __float2bfloat16(v10); g_vhi[r1] = h;
                g_vlo[r1] = __float2bfloat16(v10 - __bfloat162float(h));
                h = __float2bfloat16(v11); g_vhi[r1 + 1] = h;
                g_vlo[r1 + 1] = __float2bfloat16(v11 - __bfloat162float(h));
            }
        }
    }
}

// ------------------------------------------------------------------
// QK logits mma (unchanged).
#define QK_SMEM_BYTES 65536

__global__ void __launch_bounds__(256) qk_mma_kernel(
    const float* __restrict__ ab, const int* __restrict__ bidx)
{
    extern __shared__ __align__(1024) char smem[];
    const uint32_t sb = s2u(smem);
    const int tid = threadIdx.x;
    const int wid = tid >> 5, lane = tid & 31;
    const int warp_m = wid & 1;
    const int warp_n = wid >> 1;
    const int bh = blockIdx.z;
    const int b = bh >> 3, h = bh & 7;
    const int n0 = blockIdx.x * 128;
    const int m0c = blockIdx.y * 128;

    const __nv_bfloat16* Qhi = g_qkh_hi + (size_t)(b * 16 + h) * 196 * 32;
    const __nv_bfloat16* Qlo = g_qkh_lo + (size_t)(b * 16 + h) * 196 * 32;
    const __nv_bfloat16* Khi = g_qkh_hi + (size_t)(b * 16 + 8 + h) * 196 * 32;
    const __nv_bfloat16* Klo = g_qkh_lo + (size_t)(b * 16 + 8 + h) * 196 * 32;

#pragma unroll
    for (int t = 0; t < 2; t++) {
        int q = tid + (t << 8);
        int row = q >> 2, k8 = q & 3;
        uint32_t off = (uint32_t)(row * 128 + k8 * 16);
        uint32_t sw = off ^ ((off >> 3) & 0x70);
        int nr = n0 + row;
        int vq = nr < 196;
        size_t gq = vq ? ((size_t)nr * 32 + (k8 << 3)) : 0;
        cp_async16_zf(sb + sw,           Qhi + gq, vq);
        cp_async16_zf(sb + 16384u + sw,  Qlo + gq, vq);
        int mr = m0c + row;
        int vk = mr < 196;
        size_t gk = vk ? ((size_t)mr * 32 + (k8 << 3)) : 0;
        cp_async16_zf(sb + 32768u + sw,  Khi + gk, vk);
        cp_async16_zf(sb + 49152u + sw,  Klo + gk, vk);
    }
    asm volatile("cp.async.commit_group;" ::: "memory");
    asm volatile("cp.async.wait_group 0;" ::: "memory");
    __syncthreads();

    float acc[4][4][4];
#pragma unroll
    for (int i = 0; i < 4; i++)
#pragma unroll
        for (int j = 0; j < 4; j++)
#pragma unroll
            for (int c = 0; c < 4; c++) acc[i][j][c] = 0.f;

    const int lrow = lane & 15;
    const uint32_t lkoff = (uint32_t)((lane >> 4) << 4);

#pragma unroll
    for (int ks = 0; ks < 2; ks++) {
        uint32_t bh_[4][2], bl_[4][2];
#pragma unroll
        for (int p = 0; p < 2; p++) {
            uint32_t off = (uint32_t)((warp_n * 32 + p * 16 + lrow) * 128)
                         + (uint32_t)(ks * 32) + lkoff;
            uint32_t sw = off ^ ((off >> 3) & 0x70);
            uint32_t r0, r1, r2, r3;
            ldmat_x4(r0, r1, r2, r3, sb + 32768u + sw);
            bh_[p * 2 + 0][0] = r0; bh_[p * 2 + 1][0] = r1;
            bh_[p * 2 + 0][1] = r2; bh_[p * 2 + 1][1] = r3;
            ldmat_x4(r0, r1, r2, r3, sb + 49152u + sw);
            bl_[p * 2 + 0][0] = r0; bl_[p * 2 + 1][0] = r1;
            bl_[p * 2 + 0][1] = r2; bl_[p * 2 + 1][1] = r3;
        }
#pragma unroll
        for (int mt = 0; mt < 4; mt++) {
            uint32_t off = (uint32_t)((warp_m * 64 + mt * 16 + lrow) * 128)
                         + (uint32_t)(ks * 32) + lkoff;
            uint32_t sw = off ^ ((off >> 3) & 0x70);
            uint32_t a0, a1, a2, a3;
            ldmat_x4(a0, a1, a2, a3, sb + sw);
#pragma unroll
            for (int nt = 0; nt < 4; nt++)
                mma_bf16(acc[mt][nt][0], acc[mt][nt][1],
                         acc[mt][nt][2], acc[mt][nt][3],
                         a0, a1, a2, a3, bh_[nt][0], bh_[nt][1]);
#pragma unroll
            for (int nt = 0; nt < 4; nt++)
                mma_bf16(acc[mt][nt][0], acc[mt][nt][1],
                         acc[mt][nt][2], acc[mt][nt][3],
                         a0, a1, a2, a3, bl_[nt][0], bl_[nt][1]);
            ldmat_x4(a0, a1, a2, a3, sb + 16384u + sw);
#pragma unroll
            for (int nt = 0; nt < 4; nt++)
                mma_bf16(acc[mt][nt][0], acc[mt][nt][1],
                         acc[mt][nt][2], acc[mt][nt][3],
                         a0, a1, a2, a3, bh_[nt][0], bh_[nt][1]);
        }
    }

    const int group = lane >> 2, tig = lane & 3;
    const float* abh = ab + h * 196;
    float* lbase = g_logits + (size_t)bh * 196 * 196;
#pragma unroll
    for (int mt = 0; mt < 4; mt++) {
        int nr0 = n0 + warp_m * 64 + mt * 16 + group;
        int nr1 = nr0 + 8;
#pragma unroll
        for (int nt = 0; nt < 4; nt++) {
            int m = m0c + warp_n * 32 + nt * 8 + tig * 2;
            if (m < 196) {
                if (nr0 < 196) {
                    const int* br = bidx + (size_t)nr0 * 196;
                    lbase[(size_t)nr0 * 196 + m]     = acc[mt][nt][0] * SCALEF + abh[br[m]];
                    lbase[(size_t)nr0 * 196 + m + 1] = acc[mt][nt][1] * SCALEF + abh[br[m + 1]];
                }
                if (nr1 < 196) {
                    const int* br = bidx + (size_t)nr1 * 196;
                    lbase[(size_t)nr1 * 196 + m]     = acc[mt][nt][2] * SCALEF + abh[br[m]];
                    lbase[(size_t)nr1 * 196 + m + 1] = acc[mt][nt][3] * SCALEF + abh[br[m + 1]];
                }
            }
        }
    }
}

// ------------------------------------------------------------------
// AV batched mma (unchanged): one block per bo, single V pass.
#define AV_STAGE_BYTES 98304
#define AV_SMEM_BYTES  (2 * AV_STAGE_BYTES)

__global__ void __launch_bounds__(256) av_mma_kernel()
{
    extern __shared__ __align__(1024) char smem[];
    const uint32_t sb = s2u(smem);
    const int tid = threadIdx.x;
    const int wid = tid >> 5, lane = tid & 31;
    const int warp_m = wid & 1;
    const int warp_n = wid >> 1;
    const int bo = blockIdx.x;
    const int b  = bo >> 3, o = bo & 7;

    const __nv_bfloat16* Ahi = g_vhi + ((size_t)b * 1024 + o * 128) * KPAD;
    const __nv_bfloat16* Alo = g_vlo + ((size_t)b * 1024 + o * 128) * KPAD;
    const __nv_bfloat16* Bhi = g_phi + ((size_t)bo * 196) * KPAD;
    const __nv_bfloat16* Blo = g_plo + ((size_t)bo * 196) * KPAD;

    float acc0[4][4][4], acc1[4][4][4];
#pragma unroll
    for (int i = 0; i < 4; i++)
#pragma unroll
        for (int j = 0; j < 4; j++)
#pragma unroll
            for (int c = 0; c < 4; c++) { acc0[i][j][c] = 0.f; acc1[i][j][c] = 0.f; }

    const int lrow = lane & 15;
    const uint32_t lkoff = (uint32_t)((lane >> 4) << 4);

    auto issue = [&](int kb, uint32_t stage_off) {
#pragma unroll
        for (int i = 0; i < 4; i++) {
            int q = tid + (i << 8);
            int row = q >> 3, k8 = q & 7;
            uint32_t off = (uint32_t)(row * 128 + k8 * 16);
            uint32_t sw = off ^ ((off >> 3) & 0x70);
            size_t ga = (size_t)row * KPAD + kb + (k8 << 3);
            cp_async16(sb + stage_off + sw,          Ahi + ga);
            cp_async16(sb + stage_off + 16384u + sw, Alo + ga);
            size_t gb0 = (size_t)row * KPAD + kb + (k8 << 3);
            cp_async16(sb + stage_off + 32768u + sw, Bhi + gb0);
            cp_async16(sb + stage_off + 49152u + sw, Blo + gb0);
            int jr = 128 + row;
            int valid = jr < 196;
            size_t gb1 = valid ? ((size_t)jr * KPAD + kb + (k8 << 3)) : 0;
            cp_async16_zf(sb + stage_off + 65536u + sw, Bhi + gb1, valid);
            cp_async16_zf(sb + stage_off + 81920u + sw, Blo + gb1, valid);
        }
        asm volatile("cp.async.commit_group;" ::: "memory");
    };

    issue(0, 0u);
    issue(64, AV_STAGE_BYTES);

    for (int ch = 0; ch < 4; ch++) {
        if (ch + 1 < 4) asm volatile("cp.async.wait_group 1;" ::: "memory");
        else            asm volatile("cp.async.wait_group 0;" ::: "memory");
        __syncthreads();

        const uint32_t buf = (ch & 1) ? (uint32_t)AV_STAGE_BYTES : 0u;
        const int nks = (ch == 3) ? 1 : 4;
        for (int ks = 0; ks < nks; ks++) {
            uint32_t b0h[4][2], b0l[4][2], b1h[4][2], b1l[4][2];
#pragma unroll
            for (int p = 0; p < 2; p++) {
                uint32_t off = (uint32_t)((warp_n * 32 + p * 16 + lrow) * 128)
                             + (uint32_t)(ks * 32) + lkoff;
                uint32_t sw = off ^ ((off >> 3) & 0x70);
                uint32_t r0, r1, r2, r3;
                ldmat_x4(r0, r1, r2, r3, sb + buf + 32768u + sw);
                b0h[p * 2 + 0][0] = r0; b0h[p * 2 + 1][0] = r1;
                b0h[p * 2 + 0][1] = r2; b0h[p * 2 + 1][1] = r3;
                ldmat_x4(r0, r1, r2, r3, sb + buf + 49152u + sw);
                b0l[p * 2 + 0][0] = r0; b0l[p * 2 + 1][0] = r1;
                b0l[p * 2 + 0][1] = r2; b0l[p * 2 + 1][1] = r3;
                ldmat_x4(r0, r1, r2, r3, sb + buf + 65536u + sw);
                b1h[p * 2 + 0][0] = r0; b1h[p * 2 + 1][0] = r1;
                b1h[p * 2 + 0][1] = r2; b1h[p * 2 + 1][1] = r3;
                ldmat_x4(r0, r1, r2, r3, sb + buf + 81920u + sw);
                b1l[p * 2 + 0][0] = r0; b1l[p * 2 + 1][0] = r1;
                b1l[p * 2 + 0][1] = r2; b1l[p * 2 + 1][1] = r3;
            }
#pragma unroll
            for (int mt = 0; mt < 4; mt++) {
                uint32_t off = (uint32_t)((warp_m * 64 + mt * 16 + lrow) * 128)
                             + (uint32_t)(ks * 32) + lkoff;
                uint32_t sw = off ^ ((off >> 3) & 0x70);
                uint32_t a0, a1, a2, a3;
                ldmat_x4(a0, a1, a2, a3, sb + buf + sw);
#pragma unroll
                for (int nt = 0; nt < 4; nt++) {
                    mma_bf16(acc0[mt][nt][0], acc0[mt][nt][1],
                             acc0[mt][nt][2], acc0[mt][nt][3],
                             a0, a1, a2, a3, b0h[nt][0], b0h[nt][1]);
                    mma_bf16(acc0[mt][nt][0], acc0[mt][nt][1],
                             acc0[mt][nt][2], acc0[mt][nt][3],
                             a0, a1, a2, a3, b0l[nt][0], b0l[nt][1]);
                    mma_bf16(acc1[mt][nt][0], acc1[mt][nt][1],
                             acc1[mt][nt][2], acc1[mt][nt][3],
                             a0, a1, a2, a3, b1h[nt][0], b1h[nt][1]);
                    mma_bf16(acc1[mt][nt][0], acc1[mt][nt][1],
                             acc1[mt][nt][2], acc1[mt][nt][3],
                             a0, a1, a2, a3, b1l[nt][0], b1l[nt][1]);
                }
                ldmat_x4(a0, a1, a2, a3, sb + buf + 16384u + sw);
#pragma unroll
                for (int nt = 0; nt < 4; nt++) {
                    mma_bf16(acc0[mt][nt][0], acc0[mt][nt][1],
                             acc0[mt][nt][2], acc0[mt][nt][3],
                             a0, a1, a2, a3, b0h[nt][0], b0h[nt][1]);
                    mma_bf16(acc1[mt][nt][0], acc1[mt][nt][1],
                             acc1[mt][nt][2], acc1[mt][nt][3],
                             a0, a1, a2, a3, b1h[nt][0], b1h[nt][1]);
                }
            }
        }

        if (ch + 2 < 4) {
            __syncthreads();
            issue((ch + 2) << 6, buf);
        }
    }

    const int group = lane >> 2, tig = lane & 3;
    const float* vlbase = g_vloc + ((size_t)b * 1024 + o * 128) * NPIX;
#pragma unroll
    for (int mt = 0; mt < 4; mt++) {
        int e0 = warp_m * 64 + mt * 16 + group;
        int e1 = e0 + 8;
#pragma unroll
        for (int nt = 0; nt < 4; nt++) {
            int jb = warp_n * 32 + nt * 8 + tig * 2;
#pragma unroll
            for (int tile = 0; tile < 2; tile++) {
                int j = jb + tile * 128;
                if (j < 196) {
                    float a0v = tile ? acc1[mt][nt][0] : acc0[mt][nt][0];
                    float a1v = tile ? acc1[mt][nt][1] : acc0[mt][nt][1];
                    float a2v = tile ? acc1[mt][nt][2] : acc0[mt][nt][2];
                    float a3v = tile ? acc1[mt][nt][3] : acc0[mt][nt][3];
                    float v00 = fmaxf(a0v + vlbase[(size_t)e0 * NPIX + j],     0.f);
                    float v01 = fmaxf(a1v + vlbase[(size_t)e0 * NPIX + j + 1], 0.f);
                    float v10 = fmaxf(a2v + vlbase[(size_t)e1 * NPIX + j],     0.f);
                    float v11 = fmaxf(a3v + vlbase[(size_t)e1 * NPIX + j + 1], 0.f);
                    size_t r00 = ((size_t)(b * 196 + j))     * 1024 + o * 128 + e0;
                    size_t r01 = ((size_t)(b * 196 + j + 1)) * 1024 + o * 128 + e0;
                    __nv_bfloat16 h;
                    h = __float2bfloat16(v00); g_pt_hi[r00] = h;
                    g_pt_lo[r00] = __float2bfloat16(v00 - __bfloat162float(h));
                    h = __float2bfloat16(v01); g_pt_hi[r01] = h;
                    g_pt_lo[r01] = __float2bfloat16(v01 - __bfloat162float(h));
                    h = __float2bfloat16(v10); g_pt_hi[r00 + 8] = h;
                    g_pt_lo[r00 + 8] = __float2bfloat16(v10 - __bfloat162float(h));
                    h = __float2bfloat16(v11); g_pt_hi[r01 + 8] = h;
                    g_pt_lo[r01 + 8] = __float2bfloat16(v11 - __bfloat162float(h));
                }
            }
        }
    }
}

// ------------------------------------------------------------------
// Depthwise 3x3 conv (unchanged).
__global__ void __launch_bounds__(256) dwconv_kernel(
    const float* __restrict__ wvl, const float* __restrict__ bvl,
    const float* __restrict__ bn)
{
    int c0 = blockIdx.x * 8, b = blockIdx.y;
    __shared__ float p[8 * 256];
    __shared__ float wsh[72];
    __shared__ float cs[8], ct[8];
    int tid = threadIdx.x;
    const __nv_bfloat16* vhi = g_vhi + ((size_t)b * 1024 + c0) * KPAD;
    const __nv_bfloat16* vlo = g_vlo + ((size_t)b * 1024 + c0) * KPAD;

    for (int i = tid; i < 2048; i += 256) p[i] = 0.f;
    if (tid < 72) wsh[tid] = wvl[c0 * 9 + tid];
    if (tid < 8) {
        int c = c0 + tid;
        float s = bn[c] * rsqrtf(bn[3072 + c] + EPSF);
        cs[tid] = s;
        ct[tid] = (bvl[c] - bn[2048 + c]) * s + bn[1024 + c];
    }
    __syncthreads();

    for (int i = tid; i < 392; i += 256) {
        int c = i / 49, q = i - c * 49;
        int pix = q * 4;
        uint2 vh = *(const uint2*)(vhi + (size_t)c * KPAD + pix);
        uint2 vl = *(const uint2*)(vlo + (size_t)c * KPAD + pix);
        const __nv_bfloat162* hp = (const __nv_bfloat162*)&vh;
        const __nv_bfloat162* lp = (const __nv_bfloat162*)&vl;
        float2 h0 = __bfloat1622float2(hp[0]), h1 = __bfloat1622float2(hp[1]);
        float2 l0 = __bfloat1622float2(lp[0]), l1 = __bfloat1622float2(lp[1]);
        float vals[4] = { h0.x + l0.x, h0.y + l0.y, h1.x + l1.x, h1.y + l1.y };
        int y = pix / 14, x = pix - y * 14;
#pragma unroll
        for (int e = 0; e < 4; e++) {
            p[c * 256 + (y + 1) * 16 + (x + 1)] = vals[e];
            if (++x == 14) { x = 0; ++y; }
        }
    }
    __syncthreads();

    int w = tid >> 5, lane = tid & 31;
    if (lane < 28) {
        const float* pc = p + w * 256;
        float w00 = wsh[w * 9 + 0], w01 = wsh[w * 9 + 1], w02 = wsh[w * 9 + 2];
        float w10 = wsh[w * 9 + 3], w11 = wsh[w * 9 + 4], w12 = wsh[w * 9 + 5];
        float w20 = wsh[w * 9 + 6], w21 = wsh[w * 9 + 7], w22 = wsh[w * 9 + 8];
        float s = cs[w], t = ct[w];
        float* dst = g_vloc + (size_t)b * (DHC * NPIX) + (size_t)(c0 + w) * NPIX;
        int xr = lane >= 14;
        int x = lane - xr * 14;
#pragma unroll
        for (int it = 0; it < 7; it++) {
            int y = it * 2 + xr;
            const float* q = pc + y * 16 + x;
            float acc = w00 * q[0]  + w01 * q[1]  + w02 * q[2]
                      + w10 * q[16] + w11 * q[17] + w12 * q[18]
                      + w20 * q[32] + w21 * q[33] + w22 * q[34];
            dst[y * 14 + x] = acc * s + t;
        }
    }
}

// ------------------------------------------------------------------
// Attention core (unchanged R12/R13): paired-m vectorized TH1 / TH2+export.
#define ATTN_SMEM_FLOATS (21952 + 144)

__global__ void __launch_bounds__(256, 2) attn_kernel(
    const float* __restrict__ th1w, const float* __restrict__ th1b,
    const float* __restrict__ th2w, const float* __restrict__ th2b)
{
    extern __shared__ float sm[];
    float* L  = sm;
    float* th = sm + 21952;

    int tid = threadIdx.x;
    int b = blockIdx.y;
    int n0 = blockIdx.x * 14;

    if (tid < 64)       th[tid] = th1w[tid];
    else if (tid < 72)  th[tid] = th1b[tid - 64];
    else if (tid < 136) th[tid] = th2w[tid - 72];
    else if (tid < 144) th[tid] = th2b[tid - 136];
    __syncthreads();

    const float* lgbase = g_logits + (size_t)(b * 8) * 196 * 196;
    for (int idx = tid; idx < 1372; idx += 256) {
        int n_ = idx / 98, m = (idx - n_ * 98) * 2;
        size_t rowoff = (size_t)(n0 + n_) * 196 + m;
        float2 v[8];
#pragma unroll
        for (int hh = 0; hh < 8; hh++)
            v[hh] = *(const float2*)(lgbase + (size_t)hh * 196 * 196 + rowoff);
#pragma unroll
        for (int oo = 0; oo < 8; oo++) {
            float s0 = th[64 + oo], s1 = th[64 + oo];
#pragma unroll
            for (int hh = 0; hh < 8; hh++) {
                float w = th[oo * 8 + hh];
                s0 = fmaf(w, v[hh].x, s0);
                s1 = fmaf(w, v[hh].y, s1);
            }
            *(float2*)(L + (oo * 14 + n_) * 196 + m) = make_float2(s0, s1);
        }
    }
    __syncthreads();

    {
        int w = tid >> 5, lane = tid & 31;
        for (int r = 0; r < 14; r++) {
            float* row = L + (w * 14 + r) * 196;
            float mx = -1e30f;
            for (int m = lane; m < 196; m += 32) mx = fmaxf(mx, row[m]);
#pragma unroll
            for (int off = 16; off > 0; off >>= 1)
                mx = fmaxf(mx, __shfl_xor_sync(0xffffffffu, mx, off));
            float sum = 0.f;
            for (int m = lane; m < 196; m += 32) {
                float e = __expf(row[m] - mx);
                row[m] = e; sum += e;
            }
#pragma unroll
            for (int off = 16; off > 0; off >>= 1)
                sum += __shfl_xor_sync(0xffffffffu, sum, off);
            float inv = 1.f / sum;
            for (int m = lane; m < 196; m += 32) row[m] *= inv;
        }
    }
    __syncthreads();

    for (int idx = tid; idx < 1372; idx += 256) {
        int n_ = idx / 98, m = (idx - n_ * 98) * 2;
        float2 v[8];
#pragma unroll
        for (int hh = 0; hh < 8; hh++)
            v[hh] = *(const float2*)(L + (hh * 14 + n_) * 196 + m);
        size_t rbase = (size_t)(b * 8) * 196 + n0 + n_;
#pragma unroll
        for (int oo = 0; oo < 8; oo++) {
            float s0 = th[136 + oo], s1 = th[136 + oo];
#pragma unroll
            for (int hh = 0; hh < 8; hh++) {
                float w = th[72 + oo * 8 + hh];
                s0 = fmaf(w, v[hh].x, s0);
                s1 = fmaf(w, v[hh].y, s1);
            }
            __nv_bfloat162 hi2 = __floats2bfloat162_rn(s0, s1);
            float r0 = s0 - __bfloat162float(__low2bfloat16(hi2));
            float r1 = s1 - __bfloat162float(__high2bfloat16(hi2));
            __nv_bfloat162 lo2 = __floats2bfloat162_rn(r0, r1);
            size_t row = rbase + (size_t)oo * 196;
            *(__nv_bfloat162*)(g_phi + row * KPAD + m) = hi2;
            *(__nv_bfloat162*)(g_plo + row * KPAD + m) = lo2;
        }
    }
}

// ------------------------------------------------------------------
extern "C" void kernel_launch(void* const* d_in, const int* in_sizes, int n_in,
                              void* d_out, int out_size)
{
    const float* x    = (const float*)d_in[0];
    const float* wq   = (const float*)d_in[1];
    const float* bq   = (const float*)d_in[2];
    const float* bnq  = (const float*)d_in[3];
    const float* wk   = (const float*)d_in[4];
    const float* bk   = (const float*)d_in[5];
    const float* bnk  = (const float*)d_in[6];
    const float* wv   = (const float*)d_in[7];
    const float* bv   = (const float*)d_in[8];
    const float* bnv  = (const float*)d_in[9];
    const float* wvl  = (const float*)d_in[10];
    const float* bvl  = (const float*)d_in[11];
    const float* bnvl = (const float*)d_in[12];
    const float* th1w = (const float*)d_in[13];
    const float* th1b = (const float*)d_in[14];
    const float* th2w = (const float*)d_in[15];
    const float* th2b = (const float*)d_in[16];
    const float* wp   = (const float*)d_in[17];
    const float* bp   = (const float*)d_in[18];
    const float* bnp  = (const float*)d_in[19];
    const float* ab   = (const float*)d_in[20];
    const int*   bidx = (const int*)d_in[21];
    float* out = (float*)d_out;

    const int attn_smem = ATTN_SMEM_FLOATS * (int)sizeof(float);
    cudaFuncSetAttribute(attn_kernel,
                         cudaFuncAttributeMaxDynamicSharedMemorySize, attn_smem);
    cudaFuncSetAttribute(gemm_mma_kernel,
                         cudaFuncAttributeMaxDynamicSharedMemorySize, GEMM_SMEM_BYTES);
    cudaFuncSetAttribute(av_mma_kernel,
                         cudaFuncAttributeMaxDynamicSharedMemorySize, AV_SMEM_BYTES);
    cudaFuncSetAttribute(qk_mma_kernel,
                         cudaFuncAttributeMaxDynamicSharedMemorySize, QK_SMEM_BYTES);

    __nv_bfloat16 *wqkv_hi, *wqkv_lo, *xt_hi, *xt_lo, *wp_hi, *wp_lo, *pt_hi, *pt_lo;
    __nv_bfloat16 *qkh_hi, *qkh_lo;
    float *sv, *tv;
    cudaGetSymbolAddress((void**)&wqkv_hi, g_wqkv_hi);
    cudaGetSymbolAddress((void**)&wqkv_lo, g_wqkv_lo);
    cudaGetSymbolAddress((void**)&xt_hi, g_xt_hi);
    cudaGetSymbolAddress((void**)&xt_lo, g_xt_lo);
    cudaGetSymbolAddress((void**)&wp_hi, g_wp_hi);
    cudaGetSymbolAddress((void**)&wp_lo, g_wp_lo);
    cudaGetSymbolAddress((void**)&pt_hi, g_pt_hi);
    cudaGetSymbolAddress((void**)&pt_lo, g_pt_lo);
    cudaGetSymbolAddress((void**)&qkh_hi, g_qkh_hi);
    cudaGetSymbolAddress((void**)&qkh_lo, g_qkh_lo);
    cudaGetSymbolAddress((void**)&sv, g_s);
    cudaGetSymbolAddress((void**)&tv, g_t);

    // streams/events created once, outside any capture.
    static cudaStream_t s2 = nullptr;
    static cudaEvent_t evA, evB, evC, evD;
    if (s2 == nullptr) {
        cudaStreamCreateWithFlags(&s2, cudaStreamNonBlocking);
        cudaEventCreateWithFlags(&evA, cudaEventDisableTiming);
        cudaEventCreateWithFlags(&evB, cudaEventDisableTiming);
        cudaEventCreateWithFlags(&evC, cudaEventDisableTiming);
        cudaEventCreateWithFlags(&evD, cudaEventDisableTiming);
    }

    // fork: xt_cvt on s2 || prep1 on main
    cudaEventRecord(evA, 0);
    cudaStreamWaitEvent(s2, evA, 0);
    xt_cvt_kernel<<<dim3(7, 12, 64), 256, 0, s2>>>(x);
    prep_kernel<<<1152, 256>>>(wq, wk, wv, bq, bk, bv, bp, bnq, bnk, bnv, bnp);
    cudaEventRecord(evB, s2);
    cudaStreamWaitEvent(0, evB, 0);

    // s2: prep2 (wp split + pad zeroing) overlaps the qkv GEMM on main
    prep2_kernel<<<1152, 256, 0, s2>>>(wp);

    // qkv GEMM: exports q/k (g_qkh) and V (g_vhi/g_vlo); 128x128, 2 blocks/SM
    gemm_mma_kernel<<<dim3(98, 12), 256, GEMM_SMEM_BYTES>>>(
        wqkv_hi, wqkv_lo, xt_hi, xt_lo, 384, sv, tv, nullptr, 1536, qkh_hi, qkh_lo);

    // fork: dwconv on s2 || (qk -> attn) on main
    cudaEventRecord(evC, 0);
    cudaStreamWaitEvent(s2, evC, 0);
    dwconv_kernel<<<dim3(128, 64), 256, 0, s2>>>(wvl, bvl, bnvl);
    qk_mma_kernel<<<dim3(2, 2, 512), 256, QK_SMEM_BYTES>>>(ab, bidx);
    attn_kernel<<<dim3(14, 64), 256, attn_smem>>>(th1w, th1b, th2w, th2b);
    cudaEventRecord(evD, s2);
    cudaStreamWaitEvent(0, evD, 0);

    // AV (needs attn P + dwconv vloc + prep2 pads), then projection
    av_mma_kernel<<<512, 256, AV_SMEM_BYTES>>>();
    gemm_mma_kernel<<<dim3(98, 3), 256, GEMM_SMEM_BYTES>>>(
        wp_hi, wp_lo, pt_hi, pt_lo, 1024, sv + 1536, tv + 1536, out, 384,
        nullptr, nullptr);
}

// round 15
// speedup vs baseline: 1.1358x; 1.1358x over previous
#include <cuda_runtime.h>
#include <cuda_bf16.h>
#include <cuda_fp16.h>
#include <math.h>
#include <stdint.h>

#define EPSF 1e-5f
#define SCALEF 0.17677669529663687f

#define NB   64
#define NPIX 196
#define DHC  1024
#define NCOL 12544   // 64*196
#define KPAD 208     // padded k (m) dimension for AV mma (13*16)

// ------------------------------------------------------------------
// scratch (no cudaMalloc allowed)
__device__ float g_vloc[NB * DHC * NPIX];    // [b][1024][196]
__device__ float g_logits[512 * 196 * 196];  // [(b*8+h)][n][m] post-bias logits

__device__ __align__(16) __half g_xt[NCOL * 384];             // [j][k] fp16 activations
__device__ __align__(16) __half g_pt[NCOL * 1024];            // [j][k] fp16 proj input
__device__ __align__(16) __half g_wqkv_hi[1536 * 384];        // [m][k] fp16 weights
__device__ __align__(16) __half g_wqkv_lo[1536 * 384];
__device__ __align__(16) __half g_wp_hi[384 * 1024];
__device__ __align__(16) __half g_wp_lo[384 * 1024];
// q/k export: [(b*16 + hh)][n][d=32] bf16 hi/lo; hh 0-7 = q heads, 8-15 = k heads
__device__ __align__(16) __nv_bfloat16 g_qkh_hi[NB * 16 * 196 * 32];
__device__ __align__(16) __nv_bfloat16 g_qkh_lo[NB * 16 * 196 * 32];
// attention P (post-softmax/TH2) bf16 hi/lo: [(b*8+o)*196 + n][k=KPAD] (+ tail pad)
__device__ __align__(16) __nv_bfloat16 g_phi[512 * 196 * KPAD + 128];
__device__ __align__(16) __nv_bfloat16 g_plo[512 * 196 * KPAD + 128];
// BN'd V bf16 hi/lo: [b][c(1024)][k=KPAD] (written by qkv GEMM epilogue)
__device__ __align__(16) __nv_bfloat16 g_vhi[NB * 1024 * KPAD + 128];
__device__ __align__(16) __nv_bfloat16 g_vlo[NB * 1024 * KPAD + 128];
__device__ float g_s[1920];   // folded BN scale: [0:1536) qkv, [1536:1920) proj
__device__ float g_t[1920];   // folded BN shift

// ------------------------------------------------------------------
static __device__ __forceinline__ uint32_t s2u(const void* p) {
    uint32_t a;
    asm("{ .reg .u64 t; cvta.to.shared.u64 t, %1; cvt.u32.u64 %0, t; }"
        : "=r"(a) : "l"(p));
    return a;
}

static __device__ __forceinline__ void cp_async16(uint32_t saddr, const void* gptr) {
    asm volatile("cp.async.cg.shared.global [%0], [%1], 16;"
                 :: "r"(saddr), "l"(gptr) : "memory");
}

static __device__ __forceinline__ void cp_async16_zf(uint32_t saddr, const void* gptr, int valid) {
    int sz = valid ? 16 : 0;
    asm volatile("cp.async.cg.shared.global [%0], [%1], 16, %2;"
                 :: "r"(saddr), "l"(gptr), "r"(sz) : "memory");
}

static __device__ __forceinline__ void ldmat_x4(
    uint32_t& r0, uint32_t& r1, uint32_t& r2, uint32_t& r3, uint32_t addr)
{
    asm volatile("ldmatrix.sync.aligned.m8n8.x4.shared.b16 {%0,%1,%2,%3}, [%4];"
                 : "=r"(r0), "=r"(r1), "=r"(r2), "=r"(r3) : "r"(addr));
}

static __device__ __forceinline__ void mma_bf16(
    float& d0, float& d1, float& d2, float& d3,
    uint32_t a0, uint32_t a1, uint32_t a2, uint32_t a3,
    uint32_t b0, uint32_t b1)
{
    asm volatile(
        "mma.sync.aligned.m16n8k16.row.col.f32.bf16.bf16.f32 "
        "{%0,%1,%2,%3}, {%4,%5,%6,%7}, {%8,%9}, {%0,%1,%2,%3};"
        : "+f"(d0), "+f"(d1), "+f"(d2), "+f"(d3)
        : "r"(a0), "r"(a1), "r"(a2), "r"(a3), "r"(b0), "r"(b1));
}

static __device__ __forceinline__ void mma_f16(
    float& d0, float& d1, float& d2, float& d3,
    uint32_t a0, uint32_t a1, uint32_t a2, uint32_t a3,
    uint32_t b0, uint32_t b1)
{
    asm volatile(
        "mma.sync.aligned.m16n8k16.row.col.f32.f16.f16.f32 "
        "{%0,%1,%2,%3}, {%4,%5,%6,%7}, {%8,%9}, {%0,%1,%2,%3};"
        : "+f"(d0), "+f"(d1), "+f"(d2), "+f"(d3)
        : "r"(a0), "r"(a1), "r"(a2), "r"(a3), "r"(b0), "r"(b1));
}

// ------------------------------------------------------------------
// Prep 1 (critical path): fold BN scale/shift; split qkv weights fp16 hi/lo.
__global__ void __launch_bounds__(256) prep_kernel(
    const float* __restrict__ wq, const float* __restrict__ wk,
    const float* __restrict__ wv,
    const float* __restrict__ bq, const float* __restrict__ bk,
    const float* __restrict__ bv, const float* __restrict__ bp,
    const float* __restrict__ bnq, const float* __restrict__ bnk,
    const float* __restrict__ bnv, const float* __restrict__ bnp)
{
    int idx = blockIdx.x * 256 + threadIdx.x;
    int stride = gridDim.x * 256;

    for (int i = idx; i < 1536 * 384; i += stride) {
        int m = i / 384;
        float w = (m < 256) ? wq[i]
                : (m < 512) ? wk[i - 256 * 384]
                            : wv[i - 512 * 384];
        __half h = __float2half(w);
        g_wqkv_hi[i] = h;
        g_wqkv_lo[i] = __float2half(w - __half2float(h));
    }
    if (idx < 1920) {
        const float* bn; const float* bias; int c; int C;
        if (idx < 256)       { bn = bnq; bias = bq; c = idx;        C = 256; }
        else if (idx < 512)  { bn = bnk; bias = bk; c = idx - 256;  C = 256; }
        else if (idx < 1536) { bn = bnv; bias = bv; c = idx - 512;  C = 1024; }
        else                 { bn = bnp; bias = bp; c = idx - 1536; C = 384; }
        float s = bn[c] * rsqrtf(bn[3 * C + c] + EPSF);
        g_s[idx] = s;
        g_t[idx] = (bias[c] - bn[2 * C + c]) * s + bn[C + c];
    }
}

// Prep 2 (off critical path; overlaps qkv GEMM): wp split + all pad zeroing.
__global__ void __launch_bounds__(256) prep2_kernel(const float* __restrict__ wp)
{
    int idx = blockIdx.x * 256 + threadIdx.x;
    int stride = gridDim.x * 256;

    for (int i = idx; i < 384 * 1024; i += stride) {
        float w = wp[i];
        __half h = __float2half(w);
        g_wp_hi[i] = h;
        g_wp_lo[i] = __float2half(w - __half2float(h));
    }
    for (long i = idx; i < (long)100352 * 3; i += stride) {
        long r = i / 3; int k = (int)(i % 3);
        *(unsigned long long*)((char*)g_phi + r * 416 + 392 + k * 8) = 0ull;
        *(unsigned long long*)((char*)g_plo + r * 416 + 392 + k * 8) = 0ull;
    }
    for (long i = idx; i < (long)65536 * 3; i += stride) {
        long r = i / 3; int k = (int)(i % 3);
        *(unsigned long long*)((char*)g_vhi + r * 416 + 392 + k * 8) = 0ull;
        *(unsigned long long*)((char*)g_vlo + r * 416 + 392 + k * 8) = 0ull;
    }
    if (idx < 128) {
        g_phi[512 * 196 * KPAD + idx] = __float2bfloat16(0.f);
        g_plo[512 * 196 * KPAD + idx] = __float2bfloat16(0.f);
        g_vhi[NB * 1024 * KPAD + idx] = __float2bfloat16(0.f);
        g_vlo[NB * 1024 * KPAD + idx] = __float2bfloat16(0.f);
    }
}

// ------------------------------------------------------------------
// Transpose x: [b][384][196] -> Xt[j=b*196+n][k=c] fp16
__global__ void __launch_bounds__(256) xt_cvt_kernel(const float* __restrict__ X)
{
    __shared__ float t[32][29];
    int b = blockIdx.z, c0 = blockIdx.y * 32, n0 = blockIdx.x * 28;
    int tid = threadIdx.x;
    const float* src = X + ((size_t)b * 384 + c0) * 196 + n0;
    for (int i = tid; i < 32 * 28; i += 256) {
        int ci = i / 28, nj = i - ci * 28;
        t[ci][nj] = src[(size_t)ci * 196 + nj];
    }
    __syncthreads();
    for (int i = tid; i < 32 * 28; i += 256) {
        int nj = i >> 5, ci = i & 31;
        g_xt[((size_t)(b * 196 + n0 + nj)) * 384 + c0 + ci] = __float2half(t[ci][nj]);
    }
}

// ------------------------------------------------------------------
// fp16 mma.sync GEMM v4: 2-pass (Whi*X + Wlo*X), 128x128 tile, K-chunk 32,
// 3-stage cp.async, 2 blocks/SM. SW64 swizzle (64B rows).
// smem/stage: Ahi 8K | Alo 8K | B 8K = 24K; 3 stages = 72K.
#define GEMM_STAGE_BYTES 24576
#define GEMM_SMEM_BYTES  (3 * GEMM_STAGE_BYTES)

__global__ void __launch_bounds__(256, 2) gemm_mma_kernel(
    const __half* __restrict__ Ahi, const __half* __restrict__ Alo,
    const __half* __restrict__ Bmat,
    int K, const float* __restrict__ svec, const float* __restrict__ tvec,
    float* __restrict__ out, int Cout,
    __nv_bfloat16* __restrict__ qk_hi, __nv_bfloat16* __restrict__ qk_lo)
{
    extern __shared__ __align__(1024) char smem[];
    const uint32_t sb = s2u(smem);
    const int tid = threadIdx.x;
    const int wid = tid >> 5, lane = tid & 31;
    const int warp_m = wid & 1;
    const int warp_n = wid >> 1;
    const int m0 = blockIdx.y * 128;
    const int j0 = blockIdx.x * 128;
    const int nk = K >> 5;             // 32-wide k-chunks
    const bool is_qkv = (qk_hi != nullptr);

    float acc[4][4][4];
#pragma unroll
    for (int i = 0; i < 4; i++)
#pragma unroll
        for (int j = 0; j < 4; j++)
#pragma unroll
            for (int c = 0; c < 4; c++) acc[i][j][c] = 0.f;

    const int lrow = lane & 15;
    const uint32_t lkoff = (uint32_t)((lane >> 4) << 4);

    auto issue = [&](int ch, uint32_t stage_off) {
        int kb = ch << 5;
#pragma unroll
        for (int i = 0; i < 2; i++) {
            int q = tid + (i << 8);
            int row = q >> 2, k8 = q & 3;
            uint32_t off = (uint32_t)(row * 64 + k8 * 16);
            uint32_t sw = off ^ ((off >> 3) & 0x30);
            size_t ga = (size_t)(m0 + row) * K + kb + (k8 << 3);
            size_t gb = (size_t)(j0 + row) * K + kb + (k8 << 3);
            cp_async16(sb + stage_off + sw,           Ahi + ga);
            cp_async16(sb + stage_off + 8192u + sw,   Alo + ga);
            cp_async16(sb + stage_off + 16384u + sw,  Bmat + gb);
        }
        asm volatile("cp.async.commit_group;" ::: "memory");
    };

    issue(0, 0u);
    if (nk > 1) issue(1, GEMM_STAGE_BYTES);
    if (nk > 2) issue(2, 2u * GEMM_STAGE_BYTES);

    for (int ch = 0; ch < nk; ch++) {
        if (ch + 2 < nk)      asm volatile("cp.async.wait_group 2;" ::: "memory");
        else if (ch + 1 < nk) asm volatile("cp.async.wait_group 1;" ::: "memory");
        else                  asm volatile("cp.async.wait_group 0;" ::: "memory");
        __syncthreads();

        const uint32_t buf = (uint32_t)(ch % 3) * GEMM_STAGE_BYTES;
#pragma unroll
        for (int ks = 0; ks < 2; ks++) {
            uint32_t bfr[4][2];
#pragma unroll
            for (int p = 0; p < 2; p++) {
                uint32_t off = (uint32_t)((warp_n * 32 + p * 16 + lrow) * 64)
                             + (uint32_t)(ks * 32) + lkoff;
                uint32_t sw = off ^ ((off >> 3) & 0x30);
                uint32_t r0, r1, r2, r3;
                ldmat_x4(r0, r1, r2, r3, sb + buf + 16384u + sw);
                bfr[p * 2 + 0][0] = r0; bfr[p * 2 + 1][0] = r1;
                bfr[p * 2 + 0][1] = r2; bfr[p * 2 + 1][1] = r3;
            }
#pragma unroll
            for (int mt = 0; mt < 4; mt++) {
                uint32_t off = (uint32_t)((warp_m * 64 + mt * 16 + lrow) * 64)
                             + (uint32_t)(ks * 32) + lkoff;
                uint32_t sw = off ^ ((off >> 3) & 0x30);
                uint32_t a0, a1, a2, a3;
                ldmat_x4(a0, a1, a2, a3, sb + buf + sw);
#pragma unroll
                for (int nt = 0; nt < 4; nt++)
                    mma_f16(acc[mt][nt][0], acc[mt][nt][1],
                            acc[mt][nt][2], acc[mt][nt][3],
                            a0, a1, a2, a3, bfr[nt][0], bfr[nt][1]);
                ldmat_x4(a0, a1, a2, a3, sb + buf + 8192u + sw);
#pragma unroll
                for (int nt = 0; nt < 4; nt++)
                    mma_f16(acc[mt][nt][0], acc[mt][nt][1],
                            acc[mt][nt][2], acc[mt][nt][3],
                            a0, a1, a2, a3, bfr[nt][0], bfr[nt][1]);
            }
        }

        if (ch + 3 < nk) {
            __syncthreads();
            issue(ch + 3, buf);
        }
    }

    const int group = lane >> 2, tig = lane & 3;
#pragma unroll
    for (int mt = 0; mt < 4; mt++) {
        int oc0 = m0 + warp_m * 64 + mt * 16 + group;
        int oc1 = oc0 + 8;
        float s0 = svec[oc0], t0 = tvec[oc0];
        float s1 = svec[oc1], t1 = tvec[oc1];
#pragma unroll
        for (int nt = 0; nt < 4; nt++) {
            int j = j0 + warp_n * 32 + nt * 8 + tig * 2;
            int b = j / 196, n = j - b * 196;
            float v00 = acc[mt][nt][0] * s0 + t0;
            float v01 = acc[mt][nt][1] * s0 + t0;
            float v10 = acc[mt][nt][2] * s1 + t1;
            float v11 = acc[mt][nt][3] * s1 + t1;
            if (!is_qkv) {
                float* p0 = out + ((size_t)b * Cout + oc0) * 196 + n;
                float* p1 = out + ((size_t)b * Cout + oc1) * 196 + n;
                p0[0] = v00; p0[1] = v01;
                p1[0] = v10; p1[1] = v11;
            } else if (m0 < 512) {
                size_t r0 = (((size_t)(b * 16) + (oc0 >> 5)) * 196 + n) * 32 + (oc0 & 31);
                size_t r1 = (((size_t)(b * 16) + (oc1 >> 5)) * 196 + n) * 32 + (oc1 & 31);
                __nv_bfloat16 h;
                h = __float2bfloat16(v00); qk_hi[r0] = h;
                qk_lo[r0] = __float2bfloat16(v00 - __bfloat162float(h));
                h = __float2bfloat16(v01); qk_hi[r0 + 32] = h;
                qk_lo[r0 + 32] = __float2bfloat16(v01 - __bfloat162float(h));
                h = __float2bfloat16(v10); qk_hi[r1] = h;
                qk_lo[r1] = __float2bfloat16(v10 - __bfloat162float(h));
                h = __float2bfloat16(v11); qk_hi[r1 + 32] = h;
                qk_lo[r1 + 32] = __float2bfloat16(v11 - __bfloat162float(h));
            } else {
                size_t r0 = ((size_t)b * 1024 + (oc0 - 512)) * KPAD + n;
                size_t r1 = ((size_t)b * 1024 + (oc1 - 512)) * KPAD + n;
                __nv_bfloat16 h;
                h = __float2bfloat16(v00); g_vhi[r0] = h;
                g_vlo[r0] = __float2bfloat16(v00 - __bfloat162float(h));
                h = __float2bfloat16(v01); g_vhi[r0 + 1] = h;
                g_vlo[r0 + 1] = __float2bfloat16(v01 - __bfloat162float(h));
                h = __float2bfloat16(v10); g_vhi[r1] = h;
                g_vlo[r1] = __float2bfloat16(v10 - __bfloat162float(h));
                h = __float2bfloat16(v11); g_vhi[r1 + 1] = h;
                g_vlo[r1 + 1] = __float2bfloat16(v11 - __bfloat162float(h));
            }
        }
    }
}

// ------------------------------------------------------------------
// QK logits mma (unchanged, bf16 3-pass).
#define QK_SMEM_BYTES 65536

__global__ void __launch_bounds__(256) qk_mma_kernel(
    const float* __restrict__ ab, const int* __restrict__ bidx)
{
    extern __shared__ __align__(1024) char smem[];
    const uint32_t sb = s2u(smem);
    const int tid = threadIdx.x;
    const int wid = tid >> 5, lane = tid & 31;
    const int warp_m = wid & 1;
    const int warp_n = wid >> 1;
    const int bh = blockIdx.z;
    const int b = bh >> 3, h = bh & 7;
    const int n0 = blockIdx.x * 128;
    const int m0c = blockIdx.y * 128;

    const __nv_bfloat16* Qhi = g_qkh_hi + (size_t)(b * 16 + h) * 196 * 32;
    const __nv_bfloat16* Qlo = g_qkh_lo + (size_t)(b * 16 + h) * 196 * 32;
    const __nv_bfloat16* Khi = g_qkh_hi + (size_t)(b * 16 + 8 + h) * 196 * 32;
    const __nv_bfloat16* Klo = g_qkh_lo + (size_t)(b * 16 + 8 + h) * 196 * 32;

#pragma unroll
    for (int t = 0; t < 2; t++) {
        int q = tid + (t << 8);
        int row = q >> 2, k8 = q & 3;
        uint32_t off = (uint32_t)(row * 128 + k8 * 16);
        uint32_t sw = off ^ ((off >> 3) & 0x70);
        int nr = n0 + row;
        int vq = nr < 196;
        size_t gq = vq ? ((size_t)nr * 32 + (k8 << 3)) : 0;
        cp_async16_zf(sb + sw,           Qhi + gq, vq);
        cp_async16_zf(sb + 16384u + sw,  Qlo + gq, vq);
        int mr = m0c + row;
        int vk = mr < 196;
        size_t gk = vk ? ((size_t)mr * 32 + (k8 << 3)) : 0;
        cp_async16_zf(sb + 32768u + sw,  Khi + gk, vk);
        cp_async16_zf(sb + 49152u + sw,  Klo + gk, vk);
    }
    asm volatile("cp.async.commit_group;" ::: "memory");
    asm volatile("cp.async.wait_group 0;" ::: "memory");
    __syncthreads();

    float acc[4][4][4];
#pragma unroll
    for (int i = 0; i < 4; i++)
#pragma unroll
        for (int j = 0; j < 4; j++)
#pragma unroll
            for (int c = 0; c < 4; c++) acc[i][j][c] = 0.f;

    const int lrow = lane & 15;
    const uint32_t lkoff = (uint32_t)((lane >> 4) << 4);

#pragma unroll
    for (int ks = 0; ks < 2; ks++) {
        uint32_t bh_[4][2], bl_[4][2];
#pragma unroll
        for (int p = 0; p < 2; p++) {
            uint32_t off = (uint32_t)((warp_n * 32 + p * 16 + lrow) * 128)
                         + (uint32_t)(ks * 32) + lkoff;
            uint32_t sw = off ^ ((off >> 3) & 0x70);
            uint32_t r0, r1, r2, r3;
            ldmat_x4(r0, r1, r2, r3, sb + 32768u + sw);
            bh_[p * 2 + 0][0] = r0; bh_[p * 2 + 1][0] = r1;
            bh_[p * 2 + 0][1] = r2; bh_[p * 2 + 1][1] = r3;
            ldmat_x4(r0, r1, r2, r3, sb + 49152u + sw);
            bl_[p * 2 + 0][0] = r0; bl_[p * 2 + 1][0] = r1;
            bl_[p * 2 + 0][1] = r2; bl_[p * 2 + 1][1] = r3;
        }
#pragma unroll
        for (int mt = 0; mt < 4; mt++) {
            uint32_t off = (uint32_t)((warp_m * 64 + mt * 16 + lrow) * 128)
                         + (uint32_t)(ks * 32) + lkoff;
            uint32_t sw = off ^ ((off >> 3) & 0x70);
            uint32_t a0, a1, a2, a3;
            ldmat_x4(a0, a1, a2, a3, sb + sw);
#pragma unroll
            for (int nt = 0; nt < 4; nt++)
                mma_bf16(acc[mt][nt][0], acc[mt][nt][1],
                         acc[mt][nt][2], acc[mt][nt][3],
                         a0, a1, a2, a3, bh_[nt][0], bh_[nt][1]);
#pragma unroll
            for (int nt = 0; nt < 4; nt++)
                mma_bf16(acc[mt][nt][0], acc[mt][nt][1],
                         acc[mt][nt][2], acc[mt][nt][3],
                         a0, a1, a2, a3, bl_[nt][0], bl_[nt][1]);
            ldmat_x4(a0, a1, a2, a3, sb + 16384u + sw);
#pragma unroll
            for (int nt = 0; nt < 4; nt++)
                mma_bf16(acc[mt][nt][0], acc[mt][nt][1],
                         acc[mt][nt][2], acc[mt][nt][3],
                         a0, a1, a2, a3, bh_[nt][0], bh_[nt][1]);
        }
    }

    const int group = lane >> 2, tig = lane & 3;
    const float* abh = ab + h * 196;
    float* lbase = g_logits + (size_t)bh * 196 * 196;
#pragma unroll
    for (int mt = 0; mt < 4; mt++) {
        int nr0 = n0 + warp_m * 64 + mt * 16 + group;
        int nr1 = nr0 + 8;
#pragma unroll
        for (int nt = 0; nt < 4; nt++) {
            int m = m0c + warp_n * 32 + nt * 8 + tig * 2;
            if (m < 196) {
                if (nr0 < 196) {
                    const int* br = bidx + (size_t)nr0 * 196;
                    lbase[(size_t)nr0 * 196 + m]     = acc[mt][nt][0] * SCALEF + abh[br[m]];
                    lbase[(size_t)nr0 * 196 + m + 1] = acc[mt][nt][1] * SCALEF + abh[br[m + 1]];
                }
                if (nr1 < 196) {
                    const int* br = bidx + (size_t)nr1 * 196;
                    lbase[(size_t)nr1 * 196 + m]     = acc[mt][nt][2] * SCALEF + abh[br[m]];
                    lbase[(size_t)nr1 * 196 + m + 1] = acc[mt][nt][3] * SCALEF + abh[br[m + 1]];
                }
            }
        }
    }
}

// ------------------------------------------------------------------
// AV batched mma (bf16 3-pass, unchanged mainloop): one block per bo.
// Epilogue writes single fp16 g_pt (proj input).
#define AV_STAGE_BYTES 98304
#define AV_SMEM_BYTES  (2 * AV_STAGE_BYTES)

__global__ void __launch_bounds__(256) av_mma_kernel()
{
    extern __shared__ __align__(1024) char smem[];
    const uint32_t sb = s2u(smem);
    const int tid = threadIdx.x;
    const int wid = tid >> 5, lane = tid & 31;
    const int warp_m = wid & 1;
    const int warp_n = wid >> 1;
    const int bo = blockIdx.x;
    const int b  = bo >> 3, o = bo & 7;

    const __nv_bfloat16* Ahi = g_vhi + ((size_t)b * 1024 + o * 128) * KPAD;
    const __nv_bfloat16* Alo = g_vlo + ((size_t)b * 1024 + o * 128) * KPAD;
    const __nv_bfloat16* Bhi = g_phi + ((size_t)bo * 196) * KPAD;
    const __nv_bfloat16* Blo = g_plo + ((size_t)bo * 196) * KPAD;

    float acc0[4][4][4], acc1[4][4][4];
#pragma unroll
    for (int i = 0; i < 4; i++)
#pragma unroll
        for (int j = 0; j < 4; j++)
#pragma unroll
            for (int c = 0; c < 4; c++) { acc0[i][j][c] = 0.f; acc1[i][j][c] = 0.f; }

    const int lrow = lane & 15;
    const uint32_t lkoff = (uint32_t)((lane >> 4) << 4);

    auto issue = [&](int kb, uint32_t stage_off) {
#pragma unroll
        for (int i = 0; i < 4; i++) {
            int q = tid + (i << 8);
            int row = q >> 3, k8 = q & 7;
            uint32_t off = (uint32_t)(row * 128 + k8 * 16);
            uint32_t sw = off ^ ((off >> 3) & 0x70);
            size_t ga = (size_t)row * KPAD + kb + (k8 << 3);
            cp_async16(sb + stage_off + sw,          Ahi + ga);
            cp_async16(sb + stage_off + 16384u + sw, Alo + ga);
            size_t gb0 = (size_t)row * KPAD + kb + (k8 << 3);
            cp_async16(sb + stage_off + 32768u + sw, Bhi + gb0);
            cp_async16(sb + stage_off + 49152u + sw, Blo + gb0);
            int jr = 128 + row;
            int valid = jr < 196;
            size_t gb1 = valid ? ((size_t)jr * KPAD + kb + (k8 << 3)) : 0;
            cp_async16_zf(sb + stage_off + 65536u + sw, Bhi + gb1, valid);
            cp_async16_zf(sb + stage_off + 81920u + sw, Blo + gb1, valid);
        }
        asm volatile("cp.async.commit_group;" ::: "memory");
    };

    issue(0, 0u);
    issue(64, AV_STAGE_BYTES);

    for (int ch = 0; ch < 4; ch++) {
        if (ch + 1 < 4) asm volatile("cp.async.wait_group 1;" ::: "memory");
        else            asm volatile("cp.async.wait_group 0;" ::: "memory");
        __syncthreads();

        const uint32_t buf = (ch & 1) ? (uint32_t)AV_STAGE_BYTES : 0u;
        const int nks = (ch == 3) ? 1 : 4;
        for (int ks = 0; ks < nks; ks++) {
            uint32_t b0h[4][2], b0l[4][2], b1h[4][2], b1l[4][2];
#pragma unroll
            for (int p = 0; p < 2; p++) {
                uint32_t off = (uint32_t)((warp_n * 32 + p * 16 + lrow) * 128)
                             + (uint32_t)(ks * 32) + lkoff;
                uint32_t sw = off ^ ((off >> 3) & 0x70);
                uint32_t r0, r1, r2, r3;
                ldmat_x4(r0, r1, r2, r3, sb + buf + 32768u + sw);
                b0h[p * 2 + 0][0] = r0; b0h[p * 2 + 1][0] = r1;
                b0h[p * 2 + 0][1] = r2; b0h[p * 2 + 1][1] = r3;
                ldmat_x4(r0, r1, r2, r3, sb + buf + 49152u + sw);
                b0l[p * 2 + 0][0] = r0; b0l[p * 2 + 1][0] = r1;
                b0l[p * 2 + 0][1] = r2; b0l[p * 2 + 1][1] = r3;
                ldmat_x4(r0, r1, r2, r3, sb + buf + 65536u + sw);
                b1h[p * 2 + 0][0] = r0; b1h[p * 2 + 1][0] = r1;
                b1h[p * 2 + 0][1] = r2; b1h[p * 2 + 1][1] = r3;
                ldmat_x4(r0, r1, r2, r3, sb + buf + 81920u + sw);
                b1l[p * 2 + 0][0] = r0; b1l[p * 2 + 1][0] = r1;
                b1l[p * 2 + 0][1] = r2; b1l[p * 2 + 1][1] = r3;
            }
#pragma unroll
            for (int mt = 0; mt < 4; mt++) {
                uint32_t off = (uint32_t)((warp_m * 64 + mt * 16 + lrow) * 128)
                             + (uint32_t)(ks * 32) + lkoff;
                uint32_t sw = off ^ ((off >> 3) & 0x70);
                uint32_t a0, a1, a2, a3;
                ldmat_x4(a0, a1, a2, a3, sb + buf + sw);
#pragma unroll
                for (int nt = 0; nt < 4; nt++) {
                    mma_bf16(acc0[mt][nt][0], acc0[mt][nt][1],
                             acc0[mt][nt][2], acc0[mt][nt][3],
                             a0, a1, a2, a3, b0h[nt][0], b0h[nt][1]);
                    mma_bf16(acc0[mt][nt][0], acc0[mt][nt][1],
                             acc0[mt][nt][2], acc0[mt][nt][3],
                             a0, a1, a2, a3, b0l[nt][0], b0l[nt][1]);
                    mma_bf16(acc1[mt][nt][0], acc1[mt][nt][1],
                             acc1[mt][nt][2], acc1[mt][nt][3],
                             a0, a1, a2, a3, b1h[nt][0], b1h[nt][1]);
                    mma_bf16(acc1[mt][nt][0], acc1[mt][nt][1],
                             acc1[mt][nt][2], acc1[mt][nt][3],
                             a0, a1, a2, a3, b1l[nt][0], b1l[nt][1]);
                }
                ldmat_x4(a0, a1, a2, a3, sb + buf + 16384u + sw);
#pragma unroll
                for (int nt = 0; nt < 4; nt++) {
                    mma_bf16(acc0[mt][nt][0], acc0[mt][nt][1],
                             acc0[mt][nt][2], acc0[mt][nt][3],
                             a0, a1, a2, a3, b0h[nt][0], b0h[nt][1]);
                    mma_bf16(acc1[mt][nt][0], acc1[mt][nt][1],
                             acc1[mt][nt][2], acc1[mt][nt][3],
                             a0, a1, a2, a3, b1h[nt][0], b1h[nt][1]);
                }
            }
        }

        if (ch + 2 < 4) {
            __syncthreads();
            issue((ch + 2) << 6, buf);
        }
    }

    // fused epilogue: relu(acc + v_local) -> single fp16 into g_pt
    const int group = lane >> 2, tig = lane & 3;
    const float* vlbase = g_vloc + ((size_t)b * 1024 + o * 128) * NPIX;
#pragma unroll
    for (int mt = 0; mt < 4; mt++) {
        int e0 = warp_m * 64 + mt * 16 + group;
        int e1 = e0 + 8;
#pragma unroll
        for (int nt = 0; nt < 4; nt++) {
            int jb = warp_n * 32 + nt * 8 + tig * 2;
#pragma unroll
            for (int tile = 0; tile < 2; tile++) {
                int j = jb + tile * 128;
                if (j < 196) {
                    float a0v = tile ? acc1[mt][nt][0] : acc0[mt][nt][0];
                    float a1v = tile ? acc1[mt][nt][1] : acc0[mt][nt][1];
                    float a2v = tile ? acc1[mt][nt][2] : acc0[mt][nt][2];
                    float a3v = tile ? acc1[mt][nt][3] : acc0[mt][nt][3];
                    float v00 = fmaxf(a0v + vlbase[(size_t)e0 * NPIX + j],     0.f);
                    float v01 = fmaxf(a1v + vlbase[(size_t)e0 * NPIX + j + 1], 0.f);
                    float v10 = fmaxf(a2v + vlbase[(size_t)e1 * NPIX + j],     0.f);
                    float v11 = fmaxf(a3v + vlbase[(size_t)e1 * NPIX + j + 1], 0.f);
                    size_t r00 = ((size_t)(b * 196 + j))     * 1024 + o * 128 + e0;
                    size_t r01 = ((size_t)(b * 196 + j + 1)) * 1024 + o * 128 + e0;
                    g_pt[r00]     = __float2half(v00);
                    g_pt[r01]     = __float2half(v01);
                    g_pt[r00 + 8] = __float2half(v10);
                    g_pt[r01 + 8] = __float2half(v11);
                }
            }
        }
    }
}

// ------------------------------------------------------------------
// Depthwise 3x3 conv (unchanged).
__global__ void __launch_bounds__(256) dwconv_kernel(
    const float* __restrict__ wvl, const float* __restrict__ bvl,
    const float* __restrict__ bn)
{
    int c0 = blockIdx.x * 8, b = blockIdx.y;
    __shared__ float p[8 * 256];
    __shared__ float wsh[72];
    __shared__ float cs[8], ct[8];
    int tid = threadIdx.x;
    const __nv_bfloat16* vhi = g_vhi + ((size_t)b * 1024 + c0) * KPAD;
    const __nv_bfloat16* vlo = g_vlo + ((size_t)b * 1024 + c0) * KPAD;

    for (int i = tid; i < 2048; i += 256) p[i] = 0.f;
    if (tid < 72) wsh[tid] = wvl[c0 * 9 + tid];
    if (tid < 8) {
        int c = c0 + tid;
        float s = bn[c] * rsqrtf(bn[3072 + c] + EPSF);
        cs[tid] = s;
        ct[tid] = (bvl[c] - bn[2048 + c]) * s + bn[1024 + c];
    }
    __syncthreads();

    for (int i = tid; i < 392; i += 256) {
        int c = i / 49, q = i - c * 49;
        int pix = q * 4;
        uint2 vh = *(const uint2*)(vhi + (size_t)c * KPAD + pix);
        uint2 vl = *(const uint2*)(vlo + (size_t)c * KPAD + pix);
        const __nv_bfloat162* hp = (const __nv_bfloat162*)&vh;
        const __nv_bfloat162* lp = (const __nv_bfloat162*)&vl;
        float2 h0 = __bfloat1622float2(hp[0]), h1 = __bfloat1622float2(hp[1]);
        float2 l0 = __bfloat1622float2(lp[0]), l1 = __bfloat1622float2(lp[1]);
        float vals[4] = { h0.x + l0.x, h0.y + l0.y, h1.x + l1.x, h1.y + l1.y };
        int y = pix / 14, x = pix - y * 14;
#pragma unroll
        for (int e = 0; e < 4; e++) {
            p[c * 256 + (y + 1) * 16 + (x + 1)] = vals[e];
            if (++x == 14) { x = 0; ++y; }
        }
    }
    __syncthreads();

    int w = tid >> 5, lane = tid & 31;
    if (lane < 28) {
        const float* pc = p + w * 256;
        float w00 = wsh[w * 9 + 0], w01 = wsh[w * 9 + 1], w02 = wsh[w * 9 + 2];
        float w10 = wsh[w * 9 + 3], w11 = wsh[w * 9 + 4], w12 = wsh[w * 9 + 5];
        float w20 = wsh[w * 9 + 6], w21 = wsh[w * 9 + 7], w22 = wsh[w * 9 + 8];
        float s = cs[w], t = ct[w];
        float* dst = g_vloc + (size_t)b * (DHC * NPIX) + (size_t)(c0 + w) * NPIX;
        int xr = lane >= 14;
        int x = lane - xr * 14;
#pragma unroll
        for (int it = 0; it < 7; it++) {
            int y = it * 2 + xr;
            const float* q = pc + y * 16 + x;
            float acc = w00 * q[0]  + w01 * q[1]  + w02 * q[2]
                      + w10 * q[16] + w11 * q[17] + w12 * q[18]
                      + w20 * q[32] + w21 * q[33] + w22 * q[34];
            dst[y * 14 + x] = acc * s + t;
        }
    }
}

// ------------------------------------------------------------------
// Attention core (unchanged): paired-m vectorized TH1 / TH2+export.
#define ATTN_SMEM_FLOATS (21952 + 144)

__global__ void __launch_bounds__(256, 2) attn_kernel(
    const float* __restrict__ th1w, const float* __restrict__ th1b,
    const float* __restrict__ th2w, const float* __restrict__ th2b)
{
    extern __shared__ float sm[];
    float* L  = sm;
    float* th = sm + 21952;

    int tid = threadIdx.x;
    int b = blockIdx.y;
    int n0 = blockIdx.x * 14;

    if (tid < 64)       th[tid] = th1w[tid];
    else if (tid < 72)  th[tid] = th1b[tid - 64];
    else if (tid < 136) th[tid] = th2w[tid - 72];
    else if (tid < 144) th[tid] = th2b[tid - 136];
    __syncthreads();

    const float* lgbase = g_logits + (size_t)(b * 8) * 196 * 196;
    for (int idx = tid; idx < 1372; idx += 256) {
        int n_ = idx / 98, m = (idx - n_ * 98) * 2;
        size_t rowoff = (size_t)(n0 + n_) * 196 + m;
        float2 v[8];
#pragma unroll
        for (int hh = 0; hh < 8; hh++)
            v[hh] = *(const float2*)(lgbase + (size_t)hh * 196 * 196 + rowoff);
#pragma unroll
        for (int oo = 0; oo < 8; oo++) {
            float s0 = th[64 + oo], s1 = th[64 + oo];
#pragma unroll
            for (int hh = 0; hh < 8; hh++) {
                float w = th[oo * 8 + hh];
                s0 = fmaf(w, v[hh].x, s0);
                s1 = fmaf(w, v[hh].y, s1);
            }
            *(float2*)(L + (oo * 14 + n_) * 196 + m) = make_float2(s0, s1);
        }
    }
    __syncthreads();

    {
        int w = tid >> 5, lane = tid & 31;
        for (int r = 0; r < 14; r++) {
            float* row = L + (w * 14 + r) * 196;
            float mx = -1e30f;
            for (int m = lane; m < 196; m += 32) mx = fmaxf(mx, row[m]);
#pragma unroll
            for (int off = 16; off > 0; off >>= 1)
                mx = fmaxf(mx, __shfl_xor_sync(0xffffffffu, mx, off));
            float sum = 0.f;
            for (int m = lane; m < 196; m += 32) {
                float e = __expf(row[m] - mx);
                row[m] = e; sum += e;
            }
#pragma unroll
            for (int off = 16; off > 0; off >>= 1)
                sum += __shfl_xor_sync(0xffffffffu, sum, off);
            float inv = 1.f / sum;
            for (int m = lane; m < 196; m += 32) row[m] *= inv;
        }
    }
    __syncthreads();

    for (int idx = tid; idx < 1372; idx += 256) {
        int n_ = idx / 98, m = (idx - n_ * 98) * 2;
        float2 v[8];
#pragma unroll
        for (int hh = 0; hh < 8; hh++)
            v[hh] = *(const float2*)(L + (hh * 14 + n_) * 196 + m);
        size_t rbase = (size_t)(b * 8) * 196 + n0 + n_;
#pragma unroll
        for (int oo = 0; oo < 8; oo++) {
            float s0 = th[136 + oo], s1 = th[136 + oo];
#pragma unroll
            for (int hh = 0; hh < 8; hh++) {
                float w = th[72 + oo * 8 + hh];
                s0 = fmaf(w, v[hh].x, s0);
                s1 = fmaf(w, v[hh].y, s1);
            }
            __nv_bfloat162 hi2 = __floats2bfloat162_rn(s0, s1);
            float r0 = s0 - __bfloat162float(__low2bfloat16(hi2));
            float r1 = s1 - __bfloat162float(__high2bfloat16(hi2));
            __nv_bfloat162 lo2 = __floats2bfloat162_rn(r0, r1);
            size_t row = rbase + (size_t)oo * 196;
            *(__nv_bfloat162*)(g_phi + row * KPAD + m) = hi2;
            *(__nv_bfloat162*)(g_plo + row * KPAD + m) = lo2;
        }
    }
}

// ------------------------------------------------------------------
extern "C" void kernel_launch(void* const* d_in, const int* in_sizes, int n_in,
                              void* d_out, int out_size)
{
    const float* x    = (const float*)d_in[0];
    const float* wq   = (const float*)d_in[1];
    const float* bq   = (const float*)d_in[2];
    const float* bnq  = (const float*)d_in[3];
    const float* wk   = (const float*)d_in[4];
    const float* bk   = (const float*)d_in[5];
    const float* bnk  = (const float*)d_in[6];
    const float* wv   = (const float*)d_in[7];
    const float* bv   = (const float*)d_in[8];
    const float* bnv  = (const float*)d_in[9];
    const float* wvl  = (const float*)d_in[10];
    const float* bvl  = (const float*)d_in[11];
    const float* bnvl = (const float*)d_in[12];
    const float* th1w = (const float*)d_in[13];
    const float* th1b = (const float*)d_in[14];
    const float* th2w = (const float*)d_in[15];
    const float* th2b = (const float*)d_in[16];
    const float* wp   = (const float*)d_in[17];
    const float* bp   = (const float*)d_in[18];
    const float* bnp  = (const float*)d_in[19];
    const float* ab   = (const float*)d_in[20];
    const int*   bidx = (const int*)d_in[21];
    float* out = (float*)d_out;

    const int attn_smem = ATTN_SMEM_FLOATS * (int)sizeof(float);
    cudaFuncSetAttribute(attn_kernel,
                         cudaFuncAttributeMaxDynamicSharedMemorySize, attn_smem);
    cudaFuncSetAttribute(gemm_mma_kernel,
                         cudaFuncAttributeMaxDynamicSharedMemorySize, GEMM_SMEM_BYTES);
    cudaFuncSetAttribute(av_mma_kernel,
                         cudaFuncAttributeMaxDynamicSharedMemorySize, AV_SMEM_BYTES);
    cudaFuncSetAttribute(qk_mma_kernel,
                         cudaFuncAttributeMaxDynamicSharedMemorySize, QK_SMEM_BYTES);

    __half *wqkv_hi, *wqkv_lo, *xt, *wp_hi, *wp_lo, *pt;
    __nv_bfloat16 *qkh_hi, *qkh_lo;
    float *sv, *tv;
    cudaGetSymbolAddress((void**)&wqkv_hi, g_wqkv_hi);
    cudaGetSymbolAddress((void**)&wqkv_lo, g_wqkv_lo);
    cudaGetSymbolAddress((void**)&xt, g_xt);
    cudaGetSymbolAddress((void**)&wp_hi, g_wp_hi);
    cudaGetSymbolAddress((void**)&wp_lo, g_wp_lo);
    cudaGetSymbolAddress((void**)&pt, g_pt);
    cudaGetSymbolAddress((void**)&qkh_hi, g_qkh_hi);
    cudaGetSymbolAddress((void**)&qkh_lo, g_qkh_lo);
    cudaGetSymbolAddress((void**)&sv, g_s);
    cudaGetSymbolAddress((void**)&tv, g_t);

    // streams/events created once, outside any capture.
    static cudaStream_t s2 = nullptr;
    static cudaEvent_t evA, evB, evC, evD;
    if (s2 == nullptr) {
        cudaStreamCreateWithFlags(&s2, cudaStreamNonBlocking);
        cudaEventCreateWithFlags(&evA, cudaEventDisableTiming);
        cudaEventCreateWithFlags(&evB, cudaEventDisableTiming);
        cudaEventCreateWithFlags(&evC, cudaEventDisableTiming);
        cudaEventCreateWithFlags(&evD, cudaEventDisableTiming);
    }

    // fork: xt_cvt on s2 || prep1 on main
    cudaEventRecord(evA, 0);
    cudaStreamWaitEvent(s2, evA, 0);
    xt_cvt_kernel<<<dim3(7, 12, 64), 256, 0, s2>>>(x);
    prep_kernel<<<1152, 256>>>(wq, wk, wv, bq, bk, bv, bp, bnq, bnk, bnv, bnp);
    cudaEventRecord(evB, s2);
    cudaStreamWaitEvent(0, evB, 0);

    // s2: prep2 (wp split + pad zeroing) overlaps the qkv GEMM on main
    prep2_kernel<<<1152, 256, 0, s2>>>(wp);

    // qkv GEMM (fp16 2-pass): exports q/k (g_qkh) and V (g_vhi/g_vlo)
    gemm_mma_kernel<<<dim3(98, 12), 256, GEMM_SMEM_BYTES>>>(
        wqkv_hi, wqkv_lo, xt, 384, sv, tv, nullptr, 1536, qkh_hi, qkh_lo);

    // fork: dwconv on s2 || (qk -> attn) on main
    cudaEventRecord(evC, 0);
    cudaStreamWaitEvent(s2, evC, 0);
    dwconv_kernel<<<dim3(128, 64), 256, 0, s2>>>(wvl, bvl, bnvl);
    qk_mma_kernel<<<dim3(2, 2, 512), 256, QK_SMEM_BYTES>>>(ab, bidx);
    attn_kernel<<<dim3(14, 64), 256, attn_smem>>>(th1w, th1b, th2w, th2b);
    cudaEventRecord(evD, s2);
    cudaStreamWaitEvent(0, evD, 0);

    // AV (bf16 3-pass; epilogue writes fp16 g_pt), then proj GEMM (fp16 2-pass)
    av_mma_kernel<<<512, 256, AV_SMEM_BYTES>>>();
    gemm_mma_kernel<<<dim3(98, 3), 256, GEMM_SMEM_BYTES>>>(
        wp_hi, wp_lo, pt, 1024, sv + 1536, tv + 1536, out, 384,
        nullptr, nullptr);
}

// round 16
// speedup vs baseline: 1.2246x; 1.0782x over previous
#include <cuda_runtime.h>
#include <cuda_bf16.h>
#include <cuda_fp16.h>
#include <math.h>
#include <stdint.h>

#define EPSF 1e-5f
#define SCALEF 0.17677669529663687f

#define NB   64
#define NPIX 196
#define DHC  1024
#define NCOL 12544   // 64*196
#define KPAD 208     // padded k (m) dimension for AV mma (13*16)

// ------------------------------------------------------------------
// scratch (no cudaMalloc allowed)
__device__ float g_vloc[NB * DHC * NPIX];    // [b][1024][196]
__device__ float g_logits[512 * 196 * 196];  // [(b*8+h)][n][m] post-bias logits

__device__ __align__(16) __half g_xt[NCOL * 384];             // [j][k] fp16 activations
__device__ __align__(16) __half g_pt[NCOL * 1024];            // [j][k] fp16 proj input
__device__ __align__(16) __half g_wqkv_hi[1536 * 384];        // [m][k] fp16 weights
__device__ __align__(16) __half g_wqkv_lo[1536 * 384];
__device__ __align__(16) __half g_wp_hi[384 * 1024];
__device__ __align__(16) __half g_wp_lo[384 * 1024];
// q/k export: [(b*16 + hh)][n][d=32] bf16 hi/lo; hh 0-7 = q heads, 8-15 = k heads
__device__ __align__(16) __nv_bfloat16 g_qkh_hi[NB * 16 * 196 * 32];
__device__ __align__(16) __nv_bfloat16 g_qkh_lo[NB * 16 * 196 * 32];
// attention P (post-softmax/TH2) single fp16: [(b*8+o)*196 + n][k=KPAD] (+ tail pad)
__device__ __align__(16) __half g_pf[512 * 196 * KPAD + 128];
// BN'd V fp16 hi/lo: [b][c(1024)][k=KPAD] (written by qkv GEMM epilogue)
__device__ __align__(16) __half g_vhi[NB * 1024 * KPAD + 128];
__device__ __align__(16) __half g_vlo[NB * 1024 * KPAD + 128];
__device__ float g_s[1920];   // folded BN scale: [0:1536) qkv, [1536:1920) proj
__device__ float g_t[1920];   // folded BN shift

// ------------------------------------------------------------------
static __device__ __forceinline__ uint32_t s2u(const void* p) {
    uint32_t a;
    asm("{ .reg .u64 t; cvta.to.shared.u64 t, %1; cvt.u32.u64 %0, t; }"
        : "=r"(a) : "l"(p));
    return a;
}

static __device__ __forceinline__ void cp_async16(uint32_t saddr, const void* gptr) {
    asm volatile("cp.async.cg.shared.global [%0], [%1], 16;"
                 :: "r"(saddr), "l"(gptr) : "memory");
}

static __device__ __forceinline__ void cp_async16_zf(uint32_t saddr, const void* gptr, int valid) {
    int sz = valid ? 16 : 0;
    asm volatile("cp.async.cg.shared.global [%0], [%1], 16, %2;"
                 :: "r"(saddr), "l"(gptr), "r"(sz) : "memory");
}

static __device__ __forceinline__ void ldmat_x4(
    uint32_t& r0, uint32_t& r1, uint32_t& r2, uint32_t& r3, uint32_t addr)
{
    asm volatile("ldmatrix.sync.aligned.m8n8.x4.shared.b16 {%0,%1,%2,%3}, [%4];"
                 : "=r"(r0), "=r"(r1), "=r"(r2), "=r"(r3) : "r"(addr));
}

static __device__ __forceinline__ void mma_bf16(
    float& d0, float& d1, float& d2, float& d3,
    uint32_t a0, uint32_t a1, uint32_t a2, uint32_t a3,
    uint32_t b0, uint32_t b1)
{
    asm volatile(
        "mma.sync.aligned.m16n8k16.row.col.f32.bf16.bf16.f32 "
        "{%0,%1,%2,%3}, {%4,%5,%6,%7}, {%8,%9}, {%0,%1,%2,%3};"
        : "+f"(d0), "+f"(d1), "+f"(d2), "+f"(d3)
        : "r"(a0), "r"(a1), "r"(a2), "r"(a3), "r"(b0), "r"(b1));
}

static __device__ __forceinline__ void mma_f16(
    float& d0, float& d1, float& d2, float& d3,
    uint32_t a0, uint32_t a1, uint32_t a2, uint32_t a3,
    uint32_t b0, uint32_t b1)
{
    asm volatile(
        "mma.sync.aligned.m16n8k16.row.col.f32.f16.f16.f32 "
        "{%0,%1,%2,%3}, {%4,%5,%6,%7}, {%8,%9}, {%0,%1,%2,%3};"
        : "+f"(d0), "+f"(d1), "+f"(d2), "+f"(d3)
        : "r"(a0), "r"(a1), "r"(a2), "r"(a3), "r"(b0), "r"(b1));
}

// ------------------------------------------------------------------
// Prep 1 (critical path): fold BN scale/shift; split qkv weights fp16 hi/lo.
__global__ void __launch_bounds__(256) prep_kernel(
    const float* __restrict__ wq, const float* __restrict__ wk,
    const float* __restrict__ wv,
    const float* __restrict__ bq, const float* __restrict__ bk,
    const float* __restrict__ bv, const float* __restrict__ bp,
    const float* __restrict__ bnq, const float* __restrict__ bnk,
    const float* __restrict__ bnv, const float* __restrict__ bnp)
{
    int idx = blockIdx.x * 256 + threadIdx.x;
    int stride = gridDim.x * 256;

    for (int i = idx; i < 1536 * 384; i += stride) {
        int m = i / 384;
        float w = (m < 256) ? wq[i]
                : (m < 512) ? wk[i - 256 * 384]
                            : wv[i - 512 * 384];
        __half h = __float2half(w);
        g_wqkv_hi[i] = h;
        g_wqkv_lo[i] = __float2half(w - __half2float(h));
    }
    if (idx < 1920) {
        const float* bn; const float* bias; int c; int C;
        if (idx < 256)       { bn = bnq; bias = bq; c = idx;        C = 256; }
        else if (idx < 512)  { bn = bnk; bias = bk; c = idx - 256;  C = 256; }
        else if (idx < 1536) { bn = bnv; bias = bv; c = idx - 512;  C = 1024; }
        else                 { bn = bnp; bias = bp; c = idx - 1536; C = 384; }
        float s = bn[c] * rsqrtf(bn[3 * C + c] + EPSF);
        g_s[idx] = s;
        g_t[idx] = (bias[c] - bn[2 * C + c]) * s + bn[C + c];
    }
}

// Prep 2 (off critical path; overlaps qkv GEMM): wp split + all pad zeroing.
__global__ void __launch_bounds__(256) prep2_kernel(const float* __restrict__ wp)
{
    int idx = blockIdx.x * 256 + threadIdx.x;
    int stride = gridDim.x * 256;

    for (int i = idx; i < 384 * 1024; i += stride) {
        float w = wp[i];
        __half h = __float2half(w);
        g_wp_hi[i] = h;
        g_wp_lo[i] = __float2half(w - __half2float(h));
    }
    // zero P k-pad: rows 512*196, row stride 416B, pad = 24B at offset 392 (3 u64)
    for (long i = idx; i < (long)100352 * 3; i += stride) {
        long r = i / 3; int k = (int)(i % 3);
        *(unsigned long long*)((char*)g_pf + r * 416 + 392 + k * 8) = 0ull;
    }
    // zero V k-pad: rows 64*1024
    for (long i = idx; i < (long)65536 * 3; i += stride) {
        long r = i / 3; int k = (int)(i % 3);
        *(unsigned long long*)((char*)g_vhi + r * 416 + 392 + k * 8) = 0ull;
        *(unsigned long long*)((char*)g_vlo + r * 416 + 392 + k * 8) = 0ull;
    }
    if (idx < 128) {
        g_pf[512 * 196 * KPAD + idx]  = __float2half(0.f);
        g_vhi[NB * 1024 * KPAD + idx] = __float2half(0.f);
        g_vlo[NB * 1024 * KPAD + idx] = __float2half(0.f);
    }
}

// ------------------------------------------------------------------
// Transpose x: [b][384][196] -> Xt[j=b*196+n][k=c] fp16
__global__ void __launch_bounds__(256) xt_cvt_kernel(const float* __restrict__ X)
{
    __shared__ float t[32][29];
    int b = blockIdx.z, c0 = blockIdx.y * 32, n0 = blockIdx.x * 28;
    int tid = threadIdx.x;
    const float* src = X + ((size_t)b * 384 + c0) * 196 + n0;
    for (int i = tid; i < 32 * 28; i += 256) {
        int ci = i / 28, nj = i - ci * 28;
        t[ci][nj] = src[(size_t)ci * 196 + nj];
    }
    __syncthreads();
    for (int i = tid; i < 32 * 28; i += 256) {
        int nj = i >> 5, ci = i & 31;
        g_xt[((size_t)(b * 196 + n0 + nj)) * 384 + c0 + ci] = __float2half(t[ci][nj]);
    }
}

// ------------------------------------------------------------------
// fp16 mma.sync GEMM (unchanged R15): 2-pass, 128x128 tile, K-chunk 32,
// 3-stage cp.async, 2 blocks/SM. SW64 swizzle.
#define GEMM_STAGE_BYTES 24576
#define GEMM_SMEM_BYTES  (3 * GEMM_STAGE_BYTES)

__global__ void __launch_bounds__(256, 2) gemm_mma_kernel(
    const __half* __restrict__ Ahi, const __half* __restrict__ Alo,
    const __half* __restrict__ Bmat,
    int K, const float* __restrict__ svec, const float* __restrict__ tvec,
    float* __restrict__ out, int Cout,
    __nv_bfloat16* __restrict__ qk_hi, __nv_bfloat16* __restrict__ qk_lo)
{
    extern __shared__ __align__(1024) char smem[];
    const uint32_t sb = s2u(smem);
    const int tid = threadIdx.x;
    const int wid = tid >> 5, lane = tid & 31;
    const int warp_m = wid & 1;
    const int warp_n = wid >> 1;
    const int m0 = blockIdx.y * 128;
    const int j0 = blockIdx.x * 128;
    const int nk = K >> 5;
    const bool is_qkv = (qk_hi != nullptr);

    float acc[4][4][4];
#pragma unroll
    for (int i = 0; i < 4; i++)
#pragma unroll
        for (int j = 0; j < 4; j++)
#pragma unroll
            for (int c = 0; c < 4; c++) acc[i][j][c] = 0.f;

    const int lrow = lane & 15;
    const uint32_t lkoff = (uint32_t)((lane >> 4) << 4);

    auto issue = [&](int ch, uint32_t stage_off) {
        int kb = ch << 5;
#pragma unroll
        for (int i = 0; i < 2; i++) {
            int q = tid + (i << 8);
            int row = q >> 2, k8 = q & 3;
            uint32_t off = (uint32_t)(row * 64 + k8 * 16);
            uint32_t sw = off ^ ((off >> 3) & 0x30);
            size_t ga = (size_t)(m0 + row) * K + kb + (k8 << 3);
            size_t gb = (size_t)(j0 + row) * K + kb + (k8 << 3);
            cp_async16(sb + stage_off + sw,           Ahi + ga);
            cp_async16(sb + stage_off + 8192u + sw,   Alo + ga);
            cp_async16(sb + stage_off + 16384u + sw,  Bmat + gb);
        }
        asm volatile("cp.async.commit_group;" ::: "memory");
    };

    issue(0, 0u);
    if (nk > 1) issue(1, GEMM_STAGE_BYTES);
    if (nk > 2) issue(2, 2u * GEMM_STAGE_BYTES);

    for (int ch = 0; ch < nk; ch++) {
        if (ch + 2 < nk)      asm volatile("cp.async.wait_group 2;" ::: "memory");
        else if (ch + 1 < nk) asm volatile("cp.async.wait_group 1;" ::: "memory");
        else                  asm volatile("cp.async.wait_group 0;" ::: "memory");
        __syncthreads();

        const uint32_t buf = (uint32_t)(ch % 3) * GEMM_STAGE_BYTES;
#pragma unroll
        for (int ks = 0; ks < 2; ks++) {
            uint32_t bfr[4][2];
#pragma unroll
            for (int p = 0; p < 2; p++) {
                uint32_t off = (uint32_t)((warp_n * 32 + p * 16 + lrow) * 64)
                             + (uint32_t)(ks * 32) + lkoff;
                uint32_t sw = off ^ ((off >> 3) & 0x30);
                uint32_t r0, r1, r2, r3;
                ldmat_x4(r0, r1, r2, r3, sb + buf + 16384u + sw);
                bfr[p * 2 + 0][0] = r0; bfr[p * 2 + 1][0] = r1;
                bfr[p * 2 + 0][1] = r2; bfr[p * 2 + 1][1] = r3;
            }
#pragma unroll
            for (int mt = 0; mt < 4; mt++) {
                uint32_t off = (uint32_t)((warp_m * 64 + mt * 16 + lrow) * 64)
                             + (uint32_t)(ks * 32) + lkoff;
                uint32_t sw = off ^ ((off >> 3) & 0x30);
                uint32_t a0, a1, a2, a3;
                ldmat_x4(a0, a1, a2, a3, sb + buf + sw);
#pragma unroll
                for (int nt = 0; nt < 4; nt++)
                    mma_f16(acc[mt][nt][0], acc[mt][nt][1],
                            acc[mt][nt][2], acc[mt][nt][3],
                            a0, a1, a2, a3, bfr[nt][0], bfr[nt][1]);
                ldmat_x4(a0, a1, a2, a3, sb + buf + 8192u + sw);
#pragma unroll
                for (int nt = 0; nt < 4; nt++)
                    mma_f16(acc[mt][nt][0], acc[mt][nt][1],
                            acc[mt][nt][2], acc[mt][nt][3],
                            a0, a1, a2, a3, bfr[nt][0], bfr[nt][1]);
            }
        }

        if (ch + 3 < nk) {
            __syncthreads();
            issue(ch + 3, buf);
        }
    }

    const int group = lane >> 2, tig = lane & 3;
#pragma unroll
    for (int mt = 0; mt < 4; mt++) {
        int oc0 = m0 + warp_m * 64 + mt * 16 + group;
        int oc1 = oc0 + 8;
        float s0 = svec[oc0], t0 = tvec[oc0];
        float s1 = svec[oc1], t1 = tvec[oc1];
#pragma unroll
        for (int nt = 0; nt < 4; nt++) {
            int j = j0 + warp_n * 32 + nt * 8 + tig * 2;
            int b = j / 196, n = j - b * 196;
            float v00 = acc[mt][nt][0] * s0 + t0;
            float v01 = acc[mt][nt][1] * s0 + t0;
            float v10 = acc[mt][nt][2] * s1 + t1;
            float v11 = acc[mt][nt][3] * s1 + t1;
            if (!is_qkv) {
                float* p0 = out + ((size_t)b * Cout + oc0) * 196 + n;
                float* p1 = out + ((size_t)b * Cout + oc1) * 196 + n;
                p0[0] = v00; p0[1] = v01;
                p1[0] = v10; p1[1] = v11;
            } else if (m0 < 512) {
                size_t r0 = (((size_t)(b * 16) + (oc0 >> 5)) * 196 + n) * 32 + (oc0 & 31);
                size_t r1 = (((size_t)(b * 16) + (oc1 >> 5)) * 196 + n) * 32 + (oc1 & 31);
                __nv_bfloat16 h;
                h = __float2bfloat16(v00); qk_hi[r0] = h;
                qk_lo[r0] = __float2bfloat16(v00 - __bfloat162float(h));
                h = __float2bfloat16(v01); qk_hi[r0 + 32] = h;
                qk_lo[r0 + 32] = __float2bfloat16(v01 - __bfloat162float(h));
                h = __float2bfloat16(v10); qk_hi[r1] = h;
                qk_lo[r1] = __float2bfloat16(v10 - __bfloat162float(h));
                h = __float2bfloat16(v11); qk_hi[r1 + 32] = h;
                qk_lo[r1 + 32] = __float2bfloat16(v11 - __bfloat162float(h));
            } else {
                size_t r0 = ((size_t)b * 1024 + (oc0 - 512)) * KPAD + n;
                size_t r1 = ((size_t)b * 1024 + (oc1 - 512)) * KPAD + n;
                __half h;
                h = __float2half(v00); g_vhi[r0] = h;
                g_vlo[r0] = __float2half(v00 - __half2float(h));
                h = __float2half(v01); g_vhi[r0 + 1] = h;
                g_vlo[r0 + 1] = __float2half(v01 - __half2float(h));
                h = __float2half(v10); g_vhi[r1] = h;
                g_vlo[r1] = __float2half(v10 - __half2float(h));
                h = __float2half(v11); g_vhi[r1 + 1] = h;
                g_vlo[r1 + 1] = __float2half(v11 - __half2float(h));
            }
        }
    }
}

// ------------------------------------------------------------------
// QK logits mma (unchanged, bf16 3-pass).
#define QK_SMEM_BYTES 65536

__global__ void __launch_bounds__(256) qk_mma_kernel(
    const float* __restrict__ ab, const int* __restrict__ bidx)
{
    extern __shared__ __align__(1024) char smem[];
    const uint32_t sb = s2u(smem);
    const int tid = threadIdx.x;
    const int wid = tid >> 5, lane = tid & 31;
    const int warp_m = wid & 1;
    const int warp_n = wid >> 1;
    const int bh = blockIdx.z;
    const int b = bh >> 3, h = bh & 7;
    const int n0 = blockIdx.x * 128;
    const int m0c = blockIdx.y * 128;

    const __nv_bfloat16* Qhi = g_qkh_hi + (size_t)(b * 16 + h) * 196 * 32;
    const __nv_bfloat16* Qlo = g_qkh_lo + (size_t)(b * 16 + h) * 196 * 32;
    const __nv_bfloat16* Khi = g_qkh_hi + (size_t)(b * 16 + 8 + h) * 196 * 32;
    const __nv_bfloat16* Klo = g_qkh_lo + (size_t)(b * 16 + 8 + h) * 196 * 32;

#pragma unroll
    for (int t = 0; t < 2; t++) {
        int q = tid + (t << 8);
        int row = q >> 2, k8 = q & 3;
        uint32_t off = (uint32_t)(row * 128 + k8 * 16);
        uint32_t sw = off ^ ((off >> 3) & 0x70);
        int nr = n0 + row;
        int vq = nr < 196;
        size_t gq = vq ? ((size_t)nr * 32 + (k8 << 3)) : 0;
        cp_async16_zf(sb + sw,           Qhi + gq, vq);
        cp_async16_zf(sb + 16384u + sw,  Qlo + gq, vq);
        int mr = m0c + row;
        int vk = mr < 196;
        size_t gk = vk ? ((size_t)mr * 32 + (k8 << 3)) : 0;
        cp_async16_zf(sb + 32768u + sw,  Khi + gk, vk);
        cp_async16_zf(sb + 49152u + sw,  Klo + gk, vk);
    }
    asm volatile("cp.async.commit_group;" ::: "memory");
    asm volatile("cp.async.wait_group 0;" ::: "memory");
    __syncthreads();

    float acc[4][4][4];
#pragma unroll
    for (int i = 0; i < 4; i++)
#pragma unroll
        for (int j = 0; j < 4; j++)
#pragma unroll
            for (int c = 0; c < 4; c++) acc[i][j][c] = 0.f;

    const int lrow = lane & 15;
    const uint32_t lkoff = (uint32_t)((lane >> 4) << 4);

#pragma unroll
    for (int ks = 0; ks < 2; ks++) {
        uint32_t bh_[4][2], bl_[4][2];
#pragma unroll
        for (int p = 0; p < 2; p++) {
            uint32_t off = (uint32_t)((warp_n * 32 + p * 16 + lrow) * 128)
                         + (uint32_t)(ks * 32) + lkoff;
            uint32_t sw = off ^ ((off >> 3) & 0x70);
            uint32_t r0, r1, r2, r3;
            ldmat_x4(r0, r1, r2, r3, sb + 32768u + sw);
            bh_[p * 2 + 0][0] = r0; bh_[p * 2 + 1][0] = r1;
            bh_[p * 2 + 0][1] = r2; bh_[p * 2 + 1][1] = r3;
            ldmat_x4(r0, r1, r2, r3, sb + 49152u + sw);
            bl_[p * 2 + 0][0] = r0; bl_[p * 2 + 1][0] = r1;
            bl_[p * 2 + 0][1] = r2; bl_[p * 2 + 1][1] = r3;
        }
#pragma unroll
        for (int mt = 0; mt < 4; mt++) {
            uint32_t off = (uint32_t)((warp_m * 64 + mt * 16 + lrow) * 128)
                         + (uint32_t)(ks * 32) + lkoff;
            uint32_t sw = off ^ ((off >> 3) & 0x70);
            uint32_t a0, a1, a2, a3;
            ldmat_x4(a0, a1, a2, a3, sb + sw);
#pragma unroll
            for (int nt = 0; nt < 4; nt++)
                mma_bf16(acc[mt][nt][0], acc[mt][nt][1],
                         acc[mt][nt][2], acc[mt][nt][3],
                         a0, a1, a2, a3, bh_[nt][0], bh_[nt][1]);
#pragma unroll
            for (int nt = 0; nt < 4; nt++)
                mma_bf16(acc[mt][nt][0], acc[mt][nt][1],
                         acc[mt][nt][2], acc[mt][nt][3],
                         a0, a1, a2, a3, bl_[nt][0], bl_[nt][1]);
            ldmat_x4(a0, a1, a2, a3, sb + 16384u + sw);
#pragma unroll
            for (int nt = 0; nt < 4; nt++)
                mma_bf16(acc[mt][nt][0], acc[mt][nt][1],
                         acc[mt][nt][2], acc[mt][nt][3],
                         a0, a1, a2, a3, bh_[nt][0], bh_[nt][1]);
        }
    }

    const int group = lane >> 2, tig = lane & 3;
    const float* abh = ab + h * 196;
    float* lbase = g_logits + (size_t)bh * 196 * 196;
#pragma unroll
    for (int mt = 0; mt < 4; mt++) {
        int nr0 = n0 + warp_m * 64 + mt * 16 + group;
        int nr1 = nr0 + 8;
#pragma unroll
        for (int nt = 0; nt < 4; nt++) {
            int m = m0c + warp_n * 32 + nt * 8 + tig * 2;
            if (m < 196) {
                if (nr0 < 196) {
                    const int* br = bidx + (size_t)nr0 * 196;
                    lbase[(size_t)nr0 * 196 + m]     = acc[mt][nt][0] * SCALEF + abh[br[m]];
                    lbase[(size_t)nr0 * 196 + m + 1] = acc[mt][nt][1] * SCALEF + abh[br[m + 1]];
                }
                if (nr1 < 196) {
                    const int* br = bidx + (size_t)nr1 * 196;
                    lbase[(size_t)nr1 * 196 + m]     = acc[mt][nt][2] * SCALEF + abh[br[m]];
                    lbase[(size_t)nr1 * 196 + m + 1] = acc[mt][nt][3] * SCALEF + abh[br[m + 1]];
                }
            }
        }
    }
}

// ------------------------------------------------------------------
// AV batched mma v3: fp16 2-pass (Vhi*P + Vlo*P), P single fp16.
// One block per bo, both n-tiles resident. K = 208 (chunks 64,64,64,16).
// smem/stage: Ahi 16K | Alo 16K | B0 16K | B1 16K = 64K; 2 stages = 128K.
#define AV_STAGE_BYTES 65536
#define AV_SMEM_BYTES  (2 * AV_STAGE_BYTES)

__global__ void __launch_bounds__(256) av_mma_kernel()
{
    extern __shared__ __align__(1024) char smem[];
    const uint32_t sb = s2u(smem);
    const int tid = threadIdx.x;
    const int wid = tid >> 5, lane = tid & 31;
    const int warp_m = wid & 1;
    const int warp_n = wid >> 1;
    const int bo = blockIdx.x;
    const int b  = bo >> 3, o = bo & 7;

    const __half* Ahi = g_vhi + ((size_t)b * 1024 + o * 128) * KPAD;
    const __half* Alo = g_vlo + ((size_t)b * 1024 + o * 128) * KPAD;
    const __half* Pf  = g_pf  + ((size_t)bo * 196) * KPAD;

    float acc0[4][4][4], acc1[4][4][4];
#pragma unroll
    for (int i = 0; i < 4; i++)
#pragma unroll
        for (int j = 0; j < 4; j++)
#pragma unroll
            for (int c = 0; c < 4; c++) { acc0[i][j][c] = 0.f; acc1[i][j][c] = 0.f; }

    const int lrow = lane & 15;
    const uint32_t lkoff = (uint32_t)((lane >> 4) << 4);

    auto issue = [&](int kb, uint32_t stage_off) {
#pragma unroll
        for (int i = 0; i < 4; i++) {
            int q = tid + (i << 8);
            int row = q >> 3, k8 = q & 7;
            uint32_t off = (uint32_t)(row * 128 + k8 * 16);
            uint32_t sw = off ^ ((off >> 3) & 0x70);
            size_t ga = (size_t)row * KPAD + kb + (k8 << 3);
            cp_async16(sb + stage_off + sw,          Ahi + ga);
            cp_async16(sb + stage_off + 16384u + sw, Alo + ga);
            size_t gb0 = (size_t)row * KPAD + kb + (k8 << 3);
            cp_async16(sb + stage_off + 32768u + sw, Pf + gb0);
            int jr = 128 + row;
            int valid = jr < 196;
            size_t gb1 = valid ? ((size_t)jr * KPAD + kb + (k8 << 3)) : 0;
            cp_async16_zf(sb + stage_off + 49152u + sw, Pf + gb1, valid);
        }
        asm volatile("cp.async.commit_group;" ::: "memory");
    };

    issue(0, 0u);
    issue(64, AV_STAGE_BYTES);

    for (int ch = 0; ch < 4; ch++) {
        if (ch + 1 < 4) asm volatile("cp.async.wait_group 1;" ::: "memory");
        else            asm volatile("cp.async.wait_group 0;" ::: "memory");
        __syncthreads();

        const uint32_t buf = (ch & 1) ? (uint32_t)AV_STAGE_BYTES : 0u;
        const int nks = (ch == 3) ? 1 : 4;
        for (int ks = 0; ks < nks; ks++) {
            uint32_t b0[4][2], b1[4][2];
#pragma unroll
            for (int p = 0; p < 2; p++) {
                uint32_t off = (uint32_t)((warp_n * 32 + p * 16 + lrow) * 128)
                             + (uint32_t)(ks * 32) + lkoff;
                uint32_t sw = off ^ ((off >> 3) & 0x70);
                uint32_t r0, r1, r2, r3;
                ldmat_x4(r0, r1, r2, r3, sb + buf + 32768u + sw);
                b0[p * 2 + 0][0] = r0; b0[p * 2 + 1][0] = r1;
                b0[p * 2 + 0][1] = r2; b0[p * 2 + 1][1] = r3;
                ldmat_x4(r0, r1, r2, r3, sb + buf + 49152u + sw);
                b1[p * 2 + 0][0] = r0; b1[p * 2 + 1][0] = r1;
                b1[p * 2 + 0][1] = r2; b1[p * 2 + 1][1] = r3;
            }
#pragma unroll
            for (int mt = 0; mt < 4; mt++) {
                uint32_t off = (uint32_t)((warp_m * 64 + mt * 16 + lrow) * 128)
                             + (uint32_t)(ks * 32) + lkoff;
                uint32_t sw = off ^ ((off >> 3) & 0x70);
                uint32_t a0, a1, a2, a3;
                ldmat_x4(a0, a1, a2, a3, sb + buf + sw);
#pragma unroll
                for (int nt = 0; nt < 4; nt++) {
                    mma_f16(acc0[mt][nt][0], acc0[mt][nt][1],
                            acc0[mt][nt][2], acc0[mt][nt][3],
                            a0, a1, a2, a3, b0[nt][0], b0[nt][1]);
                    mma_f16(acc1[mt][nt][0], acc1[mt][nt][1],
                            acc1[mt][nt][2], acc1[mt][nt][3],
                            a0, a1, a2, a3, b1[nt][0], b1[nt][1]);
                }
                ldmat_x4(a0, a1, a2, a3, sb + buf + 16384u + sw);
#pragma unroll
                for (int nt = 0; nt < 4; nt++) {
                    mma_f16(acc0[mt][nt][0], acc0[mt][nt][1],
                            acc0[mt][nt][2], acc0[mt][nt][3],
                            a0, a1, a2, a3, b0[nt][0], b0[nt][1]);
                    mma_f16(acc1[mt][nt][0], acc1[mt][nt][1],
                            acc1[mt][nt][2], acc1[mt][nt][3],
                            a0, a1, a2, a3, b1[nt][0], b1[nt][1]);
                }
            }
        }

        if (ch + 2 < 4) {
            __syncthreads();
            issue((ch + 2) << 6, buf);
        }
    }

    // fused epilogue: relu(acc + v_local) -> single fp16 into g_pt
    const int group = lane >> 2, tig = lane & 3;
    const float* vlbase = g_vloc + ((size_t)b * 1024 + o * 128) * NPIX;
#pragma unroll
    for (int mt = 0; mt < 4; mt++) {
        int e0 = warp_m * 64 + mt * 16 + group;
        int e1 = e0 + 8;
#pragma unroll
        for (int nt = 0; nt < 4; nt++) {
            int jb = warp_n * 32 + nt * 8 + tig * 2;
#pragma unroll
            for (int tile = 0; tile < 2; tile++) {
                int j = jb + tile * 128;
                if (j < 196) {
                    float a0v = tile ? acc1[mt][nt][0] : acc0[mt][nt][0];
                    float a1v = tile ? acc1[mt][nt][1] : acc0[mt][nt][1];
                    float a2v = tile ? acc1[mt][nt][2] : acc0[mt][nt][2];
                    float a3v = tile ? acc1[mt][nt][3] : acc0[mt][nt][3];
                    float v00 = fmaxf(a0v + vlbase[(size_t)e0 * NPIX + j],     0.f);
                    float v01 = fmaxf(a1v + vlbase[(size_t)e0 * NPIX + j + 1], 0.f);
                    float v10 = fmaxf(a2v + vlbase[(size_t)e1 * NPIX + j],     0.f);
                    float v11 = fmaxf(a3v + vlbase[(size_t)e1 * NPIX + j + 1], 0.f);
                    size_t r00 = ((size_t)(b * 196 + j))     * 1024 + o * 128 + e0;
                    size_t r01 = ((size_t)(b * 196 + j + 1)) * 1024 + o * 128 + e0;
                    g_pt[r00]     = __float2half(v00);
                    g_pt[r01]     = __float2half(v01);
                    g_pt[r00 + 8] = __float2half(v10);
                    g_pt[r01 + 8] = __float2half(v11);
                }
            }
        }
    }
}

// ------------------------------------------------------------------
// Depthwise 3x3 conv: reads fp16 hi/lo V export.
__global__ void __launch_bounds__(256) dwconv_kernel(
    const float* __restrict__ wvl, const float* __restrict__ bvl,
    const float* __restrict__ bn)
{
    int c0 = blockIdx.x * 8, b = blockIdx.y;
    __shared__ float p[8 * 256];
    __shared__ float wsh[72];
    __shared__ float cs[8], ct[8];
    int tid = threadIdx.x;
    const __half* vhi = g_vhi + ((size_t)b * 1024 + c0) * KPAD;
    const __half* vlo = g_vlo + ((size_t)b * 1024 + c0) * KPAD;

    for (int i = tid; i < 2048; i += 256) p[i] = 0.f;
    if (tid < 72) wsh[tid] = wvl[c0 * 9 + tid];
    if (tid < 8) {
        int c = c0 + tid;
        float s = bn[c] * rsqrtf(bn[3072 + c] + EPSF);
        cs[tid] = s;
        ct[tid] = (bvl[c] - bn[2048 + c]) * s + bn[1024 + c];
    }
    __syncthreads();

    for (int i = tid; i < 392; i += 256) {
        int c = i / 49, q = i - c * 49;
        int pix = q * 4;
        uint2 vh = *(const uint2*)(vhi + (size_t)c * KPAD + pix);
        uint2 vl = *(const uint2*)(vlo + (size_t)c * KPAD + pix);
        const __half2* hp = (const __half2*)&vh;
        const __half2* lp = (const __half2*)&vl;
        float2 h0 = __half22float2(hp[0]), h1 = __half22float2(hp[1]);
        float2 l0 = __half22float2(lp[0]), l1 = __half22float2(lp[1]);
        float vals[4] = { h0.x + l0.x, h0.y + l0.y, h1.x + l1.x, h1.y + l1.y };
        int y = pix / 14, x = pix - y * 14;
#pragma unroll
        for (int e = 0; e < 4; e++) {
            p[c * 256 + (y + 1) * 16 + (x + 1)] = vals[e];
            if (++x == 14) { x = 0; ++y; }
        }
    }
    __syncthreads();

    int w = tid >> 5, lane = tid & 31;
    if (lane < 28) {
        const float* pc = p + w * 256;
        float w00 = wsh[w * 9 + 0], w01 = wsh[w * 9 + 1], w02 = wsh[w * 9 + 2];
        float w10 = wsh[w * 9 + 3], w11 = wsh[w * 9 + 4], w12 = wsh[w * 9 + 5];
        float w20 = wsh[w * 9 + 6], w21 = wsh[w * 9 + 7], w22 = wsh[w * 9 + 8];
        float s = cs[w], t = ct[w];
        float* dst = g_vloc + (size_t)b * (DHC * NPIX) + (size_t)(c0 + w) * NPIX;
        int xr = lane >= 14;
        int x = lane - xr * 14;
#pragma unroll
        for (int it = 0; it < 7; it++) {
            int y = it * 2 + xr;
            const float* q = pc + y * 16 + x;
            float acc = w00 * q[0]  + w01 * q[1]  + w02 * q[2]
                      + w10 * q[16] + w11 * q[17] + w12 * q[18]
                      + w20 * q[32] + w21 * q[33] + w22 * q[34];
            dst[y * 14 + x] = acc * s + t;
        }
    }
}

// ------------------------------------------------------------------
// Attention core: paired-m TH1 / softmax / TH2 + single-fp16 P export.
#define ATTN_SMEM_FLOATS (21952 + 144)

__global__ void __launch_bounds__(256, 2) attn_kernel(
    const float* __restrict__ th1w, const float* __restrict__ th1b,
    const float* __restrict__ th2w, const float* __restrict__ th2b)
{
    extern __shared__ float sm[];
    float* L  = sm;
    float* th = sm + 21952;

    int tid = threadIdx.x;
    int b = blockIdx.y;
    int n0 = blockIdx.x * 14;

    if (tid < 64)       th[tid] = th1w[tid];
    else if (tid < 72)  th[tid] = th1b[tid - 64];
    else if (tid < 136) th[tid] = th2w[tid - 72];
    else if (tid < 144) th[tid] = th2b[tid - 136];
    __syncthreads();

    const float* lgbase = g_logits + (size_t)(b * 8) * 196 * 196;
    for (int idx = tid; idx < 1372; idx += 256) {
        int n_ = idx / 98, m = (idx - n_ * 98) * 2;
        size_t rowoff = (size_t)(n0 + n_) * 196 + m;
        float2 v[8];
#pragma unroll
        for (int hh = 0; hh < 8; hh++)
            v[hh] = *(const float2*)(lgbase + (size_t)hh * 196 * 196 + rowoff);
#pragma unroll
        for (int oo = 0; oo < 8; oo++) {
            float s0 = th[64 + oo], s1 = th[64 + oo];
#pragma unroll
            for (int hh = 0; hh < 8; hh++) {
                float w = th[oo * 8 + hh];
                s0 = fmaf(w, v[hh].x, s0);
                s1 = fmaf(w, v[hh].y, s1);
            }
            *(float2*)(L + (oo * 14 + n_) * 196 + m) = make_float2(s0, s1);
        }
    }
    __syncthreads();

    {
        int w = tid >> 5, lane = tid & 31;
        for (int r = 0; r < 14; r++) {
            float* row = L + (w * 14 + r) * 196;
            float mx = -1e30f;
            for (int m = lane; m < 196; m += 32) mx = fmaxf(mx, row[m]);
#pragma unroll
            for (int off = 16; off > 0; off >>= 1)
                mx = fmaxf(mx, __shfl_xor_sync(0xffffffffu, mx, off));
            float sum = 0.f;
            for (int m = lane; m < 196; m += 32) {
                float e = __expf(row[m] - mx);
                row[m] = e; sum += e;
            }
#pragma unroll
            for (int off = 16; off > 0; off >>= 1)
                sum += __shfl_xor_sync(0xffffffffu, sum, off);
            float inv = 1.f / sum;
            for (int m = lane; m < 196; m += 32) row[m] *= inv;
        }
    }
    __syncthreads();

    for (int idx = tid; idx < 1372; idx += 256) {
        int n_ = idx / 98, m = (idx - n_ * 98) * 2;
        float2 v[8];
#pragma unroll
        for (int hh = 0; hh < 8; hh++)
            v[hh] = *(const float2*)(L + (hh * 14 + n_) * 196 + m);
        size_t rbase = (size_t)(b * 8) * 196 + n0 + n_;
#pragma unroll
        for (int oo = 0; oo < 8; oo++) {
            float s0 = th[136 + oo], s1 = th[136 + oo];
#pragma unroll
            for (int hh = 0; hh < 8; hh++) {
                float w = th[72 + oo * 8 + hh];
                s0 = fmaf(w, v[hh].x, s0);
                s1 = fmaf(w, v[hh].y, s1);
            }
            size_t row = rbase + (size_t)oo * 196;
            *(__half2*)(g_pf + row * KPAD + m) = __floats2half2_rn(s0, s1);
        }
    }
}

// ------------------------------------------------------------------
extern "C" void kernel_launch(void* const* d_in, const int* in_sizes, int n_in,
                              void* d_out, int out_size)
{
    const float* x    = (const float*)d_in[0];
    const float* wq   = (const float*)d_in[1];
    const float* bq   = (const float*)d_in[2];
    const float* bnq  = (const float*)d_in[3];
    const float* wk   = (const float*)d_in[4];
    const float* bk   = (const float*)d_in[5];
    const float* bnk  = (const float*)d_in[6];
    const float* wv   = (const float*)d_in[7];
    const float* bv   = (const float*)d_in[8];
    const float* bnv  = (const float*)d_in[9];
    const float* wvl  = (const float*)d_in[10];
    const float* bvl  = (const float*)d_in[11];
    const float* bnvl = (const float*)d_in[12];
    const float* th1w = (const float*)d_in[13];
    const float* th1b = (const float*)d_in[14];
    const float* th2w = (const float*)d_in[15];
    const float* th2b = (const float*)d_in[16];
    const float* wp   = (const float*)d_in[17];
    const float* bp   = (const float*)d_in[18];
    const float* bnp  = (const float*)d_in[19];
    const float* ab   = (const float*)d_in[20];
    const int*   bidx = (const int*)d_in[21];
    float* out = (float*)d_out;

    const int attn_smem = ATTN_SMEM_FLOATS * (int)sizeof(float);
    cudaFuncSetAttribute(attn_kernel,
                         cudaFuncAttributeMaxDynamicSharedMemorySize, attn_smem);
    cudaFuncSetAttribute(gemm_mma_kernel,
                         cudaFuncAttributeMaxDynamicSharedMemorySize, GEMM_SMEM_BYTES);
    cudaFuncSetAttribute(av_mma_kernel,
                         cudaFuncAttributeMaxDynamicSharedMemorySize, AV_SMEM_BYTES);
    cudaFuncSetAttribute(qk_mma_kernel,
                         cudaFuncAttributeMaxDynamicSharedMemorySize, QK_SMEM_BYTES);

    __half *wqkv_hi, *wqkv_lo, *xt, *wp_hi, *wp_lo, *pt;
    __nv_bfloat16 *qkh_hi, *qkh_lo;
    float *sv, *tv;
    cudaGetSymbolAddress((void**)&wqkv_hi, g_wqkv_hi);
    cudaGetSymbolAddress((void**)&wqkv_lo, g_wqkv_lo);
    cudaGetSymbolAddress((void**)&xt, g_xt);
    cudaGetSymbolAddress((void**)&wp_hi, g_wp_hi);
    cudaGetSymbolAddress((void**)&wp_lo, g_wp_lo);
    cudaGetSymbolAddress((void**)&pt, g_pt);
    cudaGetSymbolAddress((void**)&qkh_hi, g_qkh_hi);
    cudaGetSymbolAddress((void**)&qkh_lo, g_qkh_lo);
    cudaGetSymbolAddress((void**)&sv, g_s);
    cudaGetSymbolAddress((void**)&tv, g_t);

    // streams/events created once, outside any capture.
    static cudaStream_t s2 = nullptr;
    static cudaEvent_t evA, evB, evC, evD;
    if (s2 == nullptr) {
        cudaStreamCreateWithFlags(&s2, cudaStreamNonBlocking);
        cudaEventCreateWithFlags(&evA, cudaEventDisableTiming);
        cudaEventCreateWithFlags(&evB, cudaEventDisableTiming);
        cudaEventCreateWithFlags(&evC, cudaEventDisableTiming);
        cudaEventCreateWithFlags(&evD, cudaEventDisableTiming);
    }

    // fork: xt_cvt on s2 || prep1 on main
    cudaEventRecord(evA, 0);
    cudaStreamWaitEvent(s2, evA, 0);
    xt_cvt_kernel<<<dim3(7, 12, 64), 256, 0, s2>>>(x);
    prep_kernel<<<1152, 256>>>(wq, wk, wv, bq, bk, bv, bp, bnq, bnk, bnv, bnp);
    cudaEventRecord(evB, s2);
    cudaStreamWaitEvent(0, evB, 0);

    // s2: prep2 (wp split + pad zeroing) overlaps the qkv GEMM on main
    prep2_kernel<<<1152, 256, 0, s2>>>(wp);

    // qkv GEMM (fp16 2-pass): exports q/k (g_qkh) and V (g_vhi/g_vlo fp16)
    gemm_mma_kernel<<<dim3(98, 12), 256, GEMM_SMEM_BYTES>>>(
        wqkv_hi, wqkv_lo, xt, 384, sv, tv, nullptr, 1536, qkh_hi, qkh_lo);

    // fork: dwconv on s2 || (qk -> attn) on main
    cudaEventRecord(evC, 0);
    cudaStreamWaitEvent(s2, evC, 0);
    dwconv_kernel<<<dim3(128, 64), 256, 0, s2>>>(wvl, bvl, bnvl);
    qk_mma_kernel<<<dim3(2, 2, 512), 256, QK_SMEM_BYTES>>>(ab, bidx);
    attn_kernel<<<dim3(14, 64), 256, attn_smem>>>(th1w, th1b, th2w, th2b);
    cudaEventRecord(evD, s2);
    cudaStreamWaitEvent(0, evD, 0);

    // AV (fp16 2-pass; epilogue writes fp16 g_pt), then proj GEMM (fp16 2-pass)
    av_mma_kernel<<<512, 256, AV_SMEM_BYTES>>>();
    gemm_mma_kernel<<<dim3(98, 3), 256, GEMM_SMEM_BYTES>>>(
        wp_hi, wp_lo, pt, 1024, sv + 1536, tv + 1536, out, 384,
        nullptr, nullptr);
}

// round 17
// speedup vs baseline: 1.3347x; 1.0900x over previous
#include <cuda_runtime.h>
#include <cuda_bf16.h>
#include <cuda_fp16.h>
#include <math.h>
#include <stdint.h>

#define EPSF 1e-5f
#define SCALEF 0.17677669529663687f

#define NB   64
#define NPIX 196
#define DHC  1024
#define NCOL 12544   // 64*196
#define KPAD 208     // padded k (m) dimension for AV mma (13*16)

// ------------------------------------------------------------------
// scratch (no cudaMalloc allowed)
__device__ float g_vloc[NB * DHC * NPIX];    // [b][1024][196]
__device__ float g_logits[512 * 196 * 196];  // [(b*8+h)][n][m] post-bias logits

__device__ __align__(16) __half g_xt[NCOL * 384];             // [j][k] fp16 activations
__device__ __align__(16) __half g_pt[NCOL * 1024];            // [j][k] fp16 proj input
__device__ __align__(16) __half g_wqkv_hi[1536 * 384];        // [m][k] fp16 weights
__device__ __align__(16) __half g_wqkv_lo[1536 * 384];
__device__ __align__(16) __half g_wp_hi[384 * 1024];
__device__ __align__(16) __half g_wp_lo[384 * 1024];
// q/k export: [(b*16 + hh)][n][d=32] bf16 hi/lo; hh 0-7 = q heads, 8-15 = k heads
__device__ __align__(16) __nv_bfloat16 g_qkh_hi[NB * 16 * 196 * 32];
__device__ __align__(16) __nv_bfloat16 g_qkh_lo[NB * 16 * 196 * 32];
// attention P (post-softmax/TH2) single fp16: [(b*8+o)*196 + n][k=KPAD] (+ tail pad)
__device__ __align__(16) __half g_pf[512 * 196 * KPAD + 128];
// BN'd V single fp16: [b][c(1024)][k=KPAD] (written by qkv GEMM epilogue)
__device__ __align__(16) __half g_vhi[NB * 1024 * KPAD + 128];
__device__ float g_s[1920];   // folded BN scale: [0:1536) qkv, [1536:1920) proj
__device__ float g_t[1920];   // folded BN shift

// ------------------------------------------------------------------
static __device__ __forceinline__ uint32_t s2u(const void* p) {
    uint32_t a;
    asm("{ .reg .u64 t; cvta.to.shared.u64 t, %1; cvt.u32.u64 %0, t; }"
        : "=r"(a) : "l"(p));
    return a;
}

static __device__ __forceinline__ void cp_async16(uint32_t saddr, const void* gptr) {
    asm volatile("cp.async.cg.shared.global [%0], [%1], 16;"
                 :: "r"(saddr), "l"(gptr) : "memory");
}

static __device__ __forceinline__ void cp_async16_zf(uint32_t saddr, const void* gptr, int valid) {
    int sz = valid ? 16 : 0;
    asm volatile("cp.async.cg.shared.global [%0], [%1], 16, %2;"
                 :: "r"(saddr), "l"(gptr), "r"(sz) : "memory");
}

static __device__ __forceinline__ void ldmat_x4(
    uint32_t& r0, uint32_t& r1, uint32_t& r2, uint32_t& r3, uint32_t addr)
{
    asm volatile("ldmatrix.sync.aligned.m8n8.x4.shared.b16 {%0,%1,%2,%3}, [%4];"
                 : "=r"(r0), "=r"(r1), "=r"(r2), "=r"(r3) : "r"(addr));
}

static __device__ __forceinline__ void mma_bf16(
    float& d0, float& d1, float& d2, float& d3,
    uint32_t a0, uint32_t a1, uint32_t a2, uint32_t a3,
    uint32_t b0, uint32_t b1)
{
    asm volatile(
        "mma.sync.aligned.m16n8k16.row.col.f32.bf16.bf16.f32 "
        "{%0,%1,%2,%3}, {%4,%5,%6,%7}, {%8,%9}, {%0,%1,%2,%3};"
        : "+f"(d0), "+f"(d1), "+f"(d2), "+f"(d3)
        : "r"(a0), "r"(a1), "r"(a2), "r"(a3), "r"(b0), "r"(b1));
}

static __device__ __forceinline__ void mma_f16(
    float& d0, float& d1, float& d2, float& d3,
    uint32_t a0, uint32_t a1, uint32_t a2, uint32_t a3,
    uint32_t b0, uint32_t b1)
{
    asm volatile(
        "mma.sync.aligned.m16n8k16.row.col.f32.f16.f16.f32 "
        "{%0,%1,%2,%3}, {%4,%5,%6,%7}, {%8,%9}, {%0,%1,%2,%3};"
        : "+f"(d0), "+f"(d1), "+f"(d2), "+f"(d3)
        : "r"(a0), "r"(a1), "r"(a2), "r"(a3), "r"(b0), "r"(b1));
}

// ------------------------------------------------------------------
// Prep 1 (critical path): fold BN scale/shift; split qkv weights fp16 hi/lo.
__global__ void __launch_bounds__(256) prep_kernel(
    const float* __restrict__ wq, const float* __restrict__ wk,
    const float* __restrict__ wv,
    const float* __restrict__ bq, const float* __restrict__ bk,
    const float* __restrict__ bv, const float* __restrict__ bp,
    const float* __restrict__ bnq, const float* __restrict__ bnk,
    const float* __restrict__ bnv, const float* __restrict__ bnp)
{
    int idx = blockIdx.x * 256 + threadIdx.x;
    int stride = gridDim.x * 256;

    for (int i = idx; i < 1536 * 384; i += stride) {
        int m = i / 384;
        float w = (m < 256) ? wq[i]
                : (m < 512) ? wk[i - 256 * 384]
                            : wv[i - 512 * 384];
        __half h = __float2half(w);
        g_wqkv_hi[i] = h;
        g_wqkv_lo[i] = __float2half(w - __half2float(h));
    }
    if (idx < 1920) {
        const float* bn; const float* bias; int c; int C;
        if (idx < 256)       { bn = bnq; bias = bq; c = idx;        C = 256; }
        else if (idx < 512)  { bn = bnk; bias = bk; c = idx - 256;  C = 256; }
        else if (idx < 1536) { bn = bnv; bias = bv; c = idx - 512;  C = 1024; }
        else                 { bn = bnp; bias = bp; c = idx - 1536; C = 384; }
        float s = bn[c] * rsqrtf(bn[3 * C + c] + EPSF);
        g_s[idx] = s;
        g_t[idx] = (bias[c] - bn[2 * C + c]) * s + bn[C + c];
    }
}

// Prep 2 (off critical path; overlaps qkv GEMM): wp split + pad zeroing.
__global__ void __launch_bounds__(256) prep2_kernel(const float* __restrict__ wp)
{
    int idx = blockIdx.x * 256 + threadIdx.x;
    int stride = gridDim.x * 256;

    for (int i = idx; i < 384 * 1024; i += stride) {
        float w = wp[i];
        __half h = __float2half(w);
        g_wp_hi[i] = h;
        g_wp_lo[i] = __float2half(w - __half2float(h));
    }
    // zero P k-pad: rows 512*196, row stride 416B, pad = 24B at offset 392 (3 u64)
    for (long i = idx; i < (long)100352 * 3; i += stride) {
        long r = i / 3; int k = (int)(i % 3);
        *(unsigned long long*)((char*)g_pf + r * 416 + 392 + k * 8) = 0ull;
    }
    // zero V k-pad: rows 64*1024
    for (long i = idx; i < (long)65536 * 3; i += stride) {
        long r = i / 3; int k = (int)(i % 3);
        *(unsigned long long*)((char*)g_vhi + r * 416 + 392 + k * 8) = 0ull;
    }
    if (idx < 128) {
        g_pf[512 * 196 * KPAD + idx]  = __float2half(0.f);
        g_vhi[NB * 1024 * KPAD + idx] = __float2half(0.f);
    }
}

// ------------------------------------------------------------------
// Transpose x: [b][384][196] -> Xt[j=b*196+n][k=c] fp16
__global__ void __launch_bounds__(256) xt_cvt_kernel(const float* __restrict__ X)
{
    __shared__ float t[32][29];
    int b = blockIdx.z, c0 = blockIdx.y * 32, n0 = blockIdx.x * 28;
    int tid = threadIdx.x;
    const float* src = X + ((size_t)b * 384 + c0) * 196 + n0;
    for (int i = tid; i < 32 * 28; i += 256) {
        int ci = i / 28, nj = i - ci * 28;
        t[ci][nj] = src[(size_t)ci * 196 + nj];
    }
    __syncthreads();
    for (int i = tid; i < 32 * 28; i += 256) {
        int nj = i >> 5, ci = i & 31;
        g_xt[((size_t)(b * 196 + n0 + nj)) * 384 + c0 + ci] = __float2half(t[ci][nj]);
    }
}

// ------------------------------------------------------------------
// fp16 mma.sync GEMM (R15/R16): 2-pass, 128x128 tile, K-chunk 32,
// 3-stage cp.async, 2 blocks/SM. SW64 swizzle. V export now single fp16.
#define GEMM_STAGE_BYTES 24576
#define GEMM_SMEM_BYTES  (3 * GEMM_STAGE_BYTES)

__global__ void __launch_bounds__(256, 2) gemm_mma_kernel(
    const __half* __restrict__ Ahi, const __half* __restrict__ Alo,
    const __half* __restrict__ Bmat,
    int K, const float* __restrict__ svec, const float* __restrict__ tvec,
    float* __restrict__ out, int Cout,
    __nv_bfloat16* __restrict__ qk_hi, __nv_bfloat16* __restrict__ qk_lo)
{
    extern __shared__ __align__(1024) char smem[];
    const uint32_t sb = s2u(smem);
    const int tid = threadIdx.x;
    const int wid = tid >> 5, lane = tid & 31;
    const int warp_m = wid & 1;
    const int warp_n = wid >> 1;
    const int m0 = blockIdx.y * 128;
    const int j0 = blockIdx.x * 128;
    const int nk = K >> 5;
    const bool is_qkv = (qk_hi != nullptr);

    float acc[4][4][4];
#pragma unroll
    for (int i = 0; i < 4; i++)
#pragma unroll
        for (int j = 0; j < 4; j++)
#pragma unroll
            for (int c = 0; c < 4; c++) acc[i][j][c] = 0.f;

    const int lrow = lane & 15;
    const uint32_t lkoff = (uint32_t)((lane >> 4) << 4);

    auto issue = [&](int ch, uint32_t stage_off) {
        int kb = ch << 5;
#pragma unroll
        for (int i = 0; i < 2; i++) {
            int q = tid + (i << 8);
            int row = q >> 2, k8 = q & 3;
            uint32_t off = (uint32_t)(row * 64 + k8 * 16);
            uint32_t sw = off ^ ((off >> 3) & 0x30);
            size_t ga = (size_t)(m0 + row) * K + kb + (k8 << 3);
            size_t gb = (size_t)(j0 + row) * K + kb + (k8 << 3);
            cp_async16(sb + stage_off + sw,           Ahi + ga);
            cp_async16(sb + stage_off + 8192u + sw,   Alo + ga);
            cp_async16(sb + stage_off + 16384u + sw,  Bmat + gb);
        }
        asm volatile("cp.async.commit_group;" ::: "memory");
    };

    issue(0, 0u);
    if (nk > 1) issue(1, GEMM_STAGE_BYTES);
    if (nk > 2) issue(2, 2u * GEMM_STAGE_BYTES);

    for (int ch = 0; ch < nk; ch++) {
        if (ch + 2 < nk)      asm volatile("cp.async.wait_group 2;" ::: "memory");
        else if (ch + 1 < nk) asm volatile("cp.async.wait_group 1;" ::: "memory");
        else                  asm volatile("cp.async.wait_group 0;" ::: "memory");
        __syncthreads();

        const uint32_t buf = (uint32_t)(ch % 3) * GEMM_STAGE_BYTES;
#pragma unroll
        for (int ks = 0; ks < 2; ks++) {
            uint32_t bfr[4][2];
#pragma unroll
            for (int p = 0; p < 2; p++) {
                uint32_t off = (uint32_t)((warp_n * 32 + p * 16 + lrow) * 64)
                             + (uint32_t)(ks * 32) + lkoff;
                uint32_t sw = off ^ ((off >> 3) & 0x30);
                uint32_t r0, r1, r2, r3;
                ldmat_x4(r0, r1, r2, r3, sb + buf + 16384u + sw);
                bfr[p * 2 + 0][0] = r0; bfr[p * 2 + 1][0] = r1;
                bfr[p * 2 + 0][1] = r2; bfr[p * 2 + 1][1] = r3;
            }
#pragma unroll
            for (int mt = 0; mt < 4; mt++) {
                uint32_t off = (uint32_t)((warp_m * 64 + mt * 16 + lrow) * 64)
                             + (uint32_t)(ks * 32) + lkoff;
                uint32_t sw = off ^ ((off >> 3) & 0x30);
                uint32_t a0, a1, a2, a3;
                ldmat_x4(a0, a1, a2, a3, sb + buf + sw);
#pragma unroll
                for (int nt = 0; nt < 4; nt++)
                    mma_f16(acc[mt][nt][0], acc[mt][nt][1],
                            acc[mt][nt][2], acc[mt][nt][3],
                            a0, a1, a2, a3, bfr[nt][0], bfr[nt][1]);
                ldmat_x4(a0, a1, a2, a3, sb + buf + 8192u + sw);
#pragma unroll
                for (int nt = 0; nt < 4; nt++)
                    mma_f16(acc[mt][nt][0], acc[mt][nt][1],
                            acc[mt][nt][2], acc[mt][nt][3],
                            a0, a1, a2, a3, bfr[nt][0], bfr[nt][1]);
            }
        }

        if (ch + 3 < nk) {
            __syncthreads();
            issue(ch + 3, buf);
        }
    }

    const int group = lane >> 2, tig = lane & 3;
#pragma unroll
    for (int mt = 0; mt < 4; mt++) {
        int oc0 = m0 + warp_m * 64 + mt * 16 + group;
        int oc1 = oc0 + 8;
        float s0 = svec[oc0], t0 = tvec[oc0];
        float s1 = svec[oc1], t1 = tvec[oc1];
#pragma unroll
        for (int nt = 0; nt < 4; nt++) {
            int j = j0 + warp_n * 32 + nt * 8 + tig * 2;
            int b = j / 196, n = j - b * 196;
            float v00 = acc[mt][nt][0] * s0 + t0;
            float v01 = acc[mt][nt][1] * s0 + t0;
            float v10 = acc[mt][nt][2] * s1 + t1;
            float v11 = acc[mt][nt][3] * s1 + t1;
            if (!is_qkv) {
                float* p0 = out + ((size_t)b * Cout + oc0) * 196 + n;
                float* p1 = out + ((size_t)b * Cout + oc1) * 196 + n;
                p0[0] = v00; p0[1] = v01;
                p1[0] = v10; p1[1] = v11;
            } else if (m0 < 512) {
                size_t r0 = (((size_t)(b * 16) + (oc0 >> 5)) * 196 + n) * 32 + (oc0 & 31);
                size_t r1 = (((size_t)(b * 16) + (oc1 >> 5)) * 196 + n) * 32 + (oc1 & 31);
                __nv_bfloat16 h;
                h = __float2bfloat16(v00); qk_hi[r0] = h;
                qk_lo[r0] = __float2bfloat16(v00 - __bfloat162float(h));
                h = __float2bfloat16(v01); qk_hi[r0 + 32] = h;
                qk_lo[r0 + 32] = __float2bfloat16(v01 - __bfloat162float(h));
                h = __float2bfloat16(v10); qk_hi[r1] = h;
                qk_lo[r1] = __float2bfloat16(v10 - __bfloat162float(h));
                h = __float2bfloat16(v11); qk_hi[r1 + 32] = h;
                qk_lo[r1 + 32] = __float2bfloat16(v11 - __bfloat162float(h));
            } else {
                size_t r0 = ((size_t)b * 1024 + (oc0 - 512)) * KPAD + n;
                size_t r1 = ((size_t)b * 1024 + (oc1 - 512)) * KPAD + n;
                g_vhi[r0]     = __float2half(v00);
                g_vhi[r0 + 1] = __float2half(v01);
                g_vhi[r1]     = __float2half(v10);
                g_vhi[r1 + 1] = __float2half(v11);
            }
        }
    }
}

// ------------------------------------------------------------------
// QK logits mma (unchanged, bf16 3-pass).
#define QK_SMEM_BYTES 65536

__global__ void __launch_bounds__(256) qk_mma_kernel(
    const float* __restrict__ ab, const int* __restrict__ bidx)
{
    extern __shared__ __align__(1024) char smem[];
    const uint32_t sb = s2u(smem);
    const int tid = threadIdx.x;
    const int wid = tid >> 5, lane = tid & 31;
    const int warp_m = wid & 1;
    const int warp_n = wid >> 1;
    const int bh = blockIdx.z;
    const int b = bh >> 3, h = bh & 7;
    const int n0 = blockIdx.x * 128;
    const int m0c = blockIdx.y * 128;

    const __nv_bfloat16* Qhi = g_qkh_hi + (size_t)(b * 16 + h) * 196 * 32;
    const __nv_bfloat16* Qlo = g_qkh_lo + (size_t)(b * 16 + h) * 196 * 32;
    const __nv_bfloat16* Khi = g_qkh_hi + (size_t)(b * 16 + 8 + h) * 196 * 32;
    const __nv_bfloat16* Klo = g_qkh_lo + (size_t)(b * 16 + 8 + h) * 196 * 32;

#pragma unroll
    for (int t = 0; t < 2; t++) {
        int q = tid + (t << 8);
        int row = q >> 2, k8 = q & 3;
        uint32_t off = (uint32_t)(row * 128 + k8 * 16);
        uint32_t sw = off ^ ((off >> 3) & 0x70);
        int nr = n0 + row;
        int vq = nr < 196;
        size_t gq = vq ? ((size_t)nr * 32 + (k8 << 3)) : 0;
        cp_async16_zf(sb + sw,           Qhi + gq, vq);
        cp_async16_zf(sb + 16384u + sw,  Qlo + gq, vq);
        int mr = m0c + row;
        int vk = mr < 196;
        size_t gk = vk ? ((size_t)mr * 32 + (k8 << 3)) : 0;
        cp_async16_zf(sb + 32768u + sw,  Khi + gk, vk);
        cp_async16_zf(sb + 49152u + sw,  Klo + gk, vk);
    }
    asm volatile("cp.async.commit_group;" ::: "memory");
    asm volatile("cp.async.wait_group 0;" ::: "memory");
    __syncthreads();

    float acc[4][4][4];
#pragma unroll
    for (int i = 0; i < 4; i++)
#pragma unroll
        for (int j = 0; j < 4; j++)
#pragma unroll
            for (int c = 0; c < 4; c++) acc[i][j][c] = 0.f;

    const int lrow = lane & 15;
    const uint32_t lkoff = (uint32_t)((lane >> 4) << 4);

#pragma unroll
    for (int ks = 0; ks < 2; ks++) {
        uint32_t bh_[4][2], bl_[4][2];
#pragma unroll
        for (int p = 0; p < 2; p++) {
            uint32_t off = (uint32_t)((warp_n * 32 + p * 16 + lrow) * 128)
                         + (uint32_t)(ks * 32) + lkoff;
            uint32_t sw = off ^ ((off >> 3) & 0x70);
            uint32_t r0, r1, r2, r3;
            ldmat_x4(r0, r1, r2, r3, sb + 32768u + sw);
            bh_[p * 2 + 0][0] = r0; bh_[p * 2 + 1][0] = r1;
            bh_[p * 2 + 0][1] = r2; bh_[p * 2 + 1][1] = r3;
            ldmat_x4(r0, r1, r2, r3, sb + 49152u + sw);
            bl_[p * 2 + 0][0] = r0; bl_[p * 2 + 1][0] = r1;
            bl_[p * 2 + 0][1] = r2; bl_[p * 2 + 1][1] = r3;
        }
#pragma unroll
        for (int mt = 0; mt < 4; mt++) {
            uint32_t off = (uint32_t)((warp_m * 64 + mt * 16 + lrow) * 128)
                         + (uint32_t)(ks * 32) + lkoff;
            uint32_t sw = off ^ ((off >> 3) & 0x70);
            uint32_t a0, a1, a2, a3;
            ldmat_x4(a0, a1, a2, a3, sb + sw);
#pragma unroll
            for (int nt = 0; nt < 4; nt++)
                mma_bf16(acc[mt][nt][0], acc[mt][nt][1],
                         acc[mt][nt][2], acc[mt][nt][3],
                         a0, a1, a2, a3, bh_[nt][0], bh_[nt][1]);
#pragma unroll
            for (int nt = 0; nt < 4; nt++)
                mma_bf16(acc[mt][nt][0], acc[mt][nt][1],
                         acc[mt][nt][2], acc[mt][nt][3],
                         a0, a1, a2, a3, bl_[nt][0], bl_[nt][1]);
            ldmat_x4(a0, a1, a2, a3, sb + 16384u + sw);
#pragma unroll
            for (int nt = 0; nt < 4; nt++)
                mma_bf16(acc[mt][nt][0], acc[mt][nt][1],
                         acc[mt][nt][2], acc[mt][nt][3],
                         a0, a1, a2, a3, bh_[nt][0], bh_[nt][1]);
        }
    }

    const int group = lane >> 2, tig = lane & 3;
    const float* abh = ab + h * 196;
    float* lbase = g_logits + (size_t)bh * 196 * 196;
#pragma unroll
    for (int mt = 0; mt < 4; mt++) {
        int nr0 = n0 + warp_m * 64 + mt * 16 + group;
        int nr1 = nr0 + 8;
#pragma unroll
        for (int nt = 0; nt < 4; nt++) {
            int m = m0c + warp_n * 32 + nt * 8 + tig * 2;
            if (m < 196) {
                if (nr0 < 196) {
                    const int* br = bidx + (size_t)nr0 * 196;
                    lbase[(size_t)nr0 * 196 + m]     = acc[mt][nt][0] * SCALEF + abh[br[m]];
                    lbase[(size_t)nr0 * 196 + m + 1] = acc[mt][nt][1] * SCALEF + abh[br[m + 1]];
                }
                if (nr1 < 196) {
                    const int* br = bidx + (size_t)nr1 * 196;
                    lbase[(size_t)nr1 * 196 + m]     = acc[mt][nt][2] * SCALEF + abh[br[m]];
                    lbase[(size_t)nr1 * 196 + m + 1] = acc[mt][nt][3] * SCALEF + abh[br[m + 1]];
                }
            }
        }
    }
}

// ------------------------------------------------------------------
// AV batched mma v4: single-pass fp16 (Vhi*P), P single fp16.
// One block per bo, both n-tiles resident. K = 208 (chunks 64,64,64,16).
// smem/stage: A 16K | B0 16K | B1 16K = 48K; 2 stages = 96K.
#define AV_STAGE_BYTES 49152
#define AV_SMEM_BYTES  (2 * AV_STAGE_BYTES)

__global__ void __launch_bounds__(256) av_mma_kernel()
{
    extern __shared__ __align__(1024) char smem[];
    const uint32_t sb = s2u(smem);
    const int tid = threadIdx.x;
    const int wid = tid >> 5, lane = tid & 31;
    const int warp_m = wid & 1;
    const int warp_n = wid >> 1;
    const int bo = blockIdx.x;
    const int b  = bo >> 3, o = bo & 7;

    const __half* Av = g_vhi + ((size_t)b * 1024 + o * 128) * KPAD;
    const __half* Pf = g_pf  + ((size_t)bo * 196) * KPAD;

    float acc0[4][4][4], acc1[4][4][4];
#pragma unroll
    for (int i = 0; i < 4; i++)
#pragma unroll
        for (int j = 0; j < 4; j++)
#pragma unroll
            for (int c = 0; c < 4; c++) { acc0[i][j][c] = 0.f; acc1[i][j][c] = 0.f; }

    const int lrow = lane & 15;
    const uint32_t lkoff = (uint32_t)((lane >> 4) << 4);

    auto issue = [&](int kb, uint32_t stage_off) {
#pragma unroll
        for (int i = 0; i < 4; i++) {
            int q = tid + (i << 8);
            int row = q >> 3, k8 = q & 7;
            uint32_t off = (uint32_t)(row * 128 + k8 * 16);
            uint32_t sw = off ^ ((off >> 3) & 0x70);
            size_t ga = (size_t)row * KPAD + kb + (k8 << 3);
            cp_async16(sb + stage_off + sw,          Av + ga);
            size_t gb0 = (size_t)row * KPAD + kb + (k8 << 3);
            cp_async16(sb + stage_off + 16384u + sw, Pf + gb0);
            int jr = 128 + row;
            int valid = jr < 196;
            size_t gb1 = valid ? ((size_t)jr * KPAD + kb + (k8 << 3)) : 0;
            cp_async16_zf(sb + stage_off + 32768u + sw, Pf + gb1, valid);
        }
        asm volatile("cp.async.commit_group;" ::: "memory");
    };

    issue(0, 0u);
    issue(64, AV_STAGE_BYTES);

    for (int ch = 0; ch < 4; ch++) {
        if (ch + 1 < 4) asm volatile("cp.async.wait_group 1;" ::: "memory");
        else            asm volatile("cp.async.wait_group 0;" ::: "memory");
        __syncthreads();

        const uint32_t buf = (ch & 1) ? (uint32_t)AV_STAGE_BYTES : 0u;
        const int nks = (ch == 3) ? 1 : 4;
        for (int ks = 0; ks < nks; ks++) {
            uint32_t b0[4][2], b1[4][2];
#pragma unroll
            for (int p = 0; p < 2; p++) {
                uint32_t off = (uint32_t)((warp_n * 32 + p * 16 + lrow) * 128)
                             + (uint32_t)(ks * 32) + lkoff;
                uint32_t sw = off ^ ((off >> 3) & 0x70);
                uint32_t r0, r1, r2, r3;
                ldmat_x4(r0, r1, r2, r3, sb + buf + 16384u + sw);
                b0[p * 2 + 0][0] = r0; b0[p * 2 + 1][0] = r1;
                b0[p * 2 + 0][1] = r2; b0[p * 2 + 1][1] = r3;
                ldmat_x4(r0, r1, r2, r3, sb + buf + 32768u + sw);
                b1[p * 2 + 0][0] = r0; b1[p * 2 + 1][0] = r1;
                b1[p * 2 + 0][1] = r2; b1[p * 2 + 1][1] = r3;
            }
#pragma unroll
            for (int mt = 0; mt < 4; mt++) {
                uint32_t off = (uint32_t)((warp_m * 64 + mt * 16 + lrow) * 128)
                             + (uint32_t)(ks * 32) + lkoff;
                uint32_t sw = off ^ ((off >> 3) & 0x70);
                uint32_t a0, a1, a2, a3;
                ldmat_x4(a0, a1, a2, a3, sb + buf + sw);
#pragma unroll
                for (int nt = 0; nt < 4; nt++) {
                    mma_f16(acc0[mt][nt][0], acc0[mt][nt][1],
                            acc0[mt][nt][2], acc0[mt][nt][3],
                            a0, a1, a2, a3, b0[nt][0], b0[nt][1]);
                    mma_f16(acc1[mt][nt][0], acc1[mt][nt][1],
                            acc1[mt][nt][2], acc1[mt][nt][3],
                            a0, a1, a2, a3, b1[nt][0], b1[nt][1]);
                }
            }
        }

        if (ch + 2 < 4) {
            __syncthreads();
            issue((ch + 2) << 6, buf);
        }
    }

    // fused epilogue: relu(acc + v_local) -> single fp16 into g_pt
    const int group = lane >> 2, tig = lane & 3;
    const float* vlbase = g_vloc + ((size_t)b * 1024 + o * 128) * NPIX;
#pragma unroll
    for (int mt = 0; mt < 4; mt++) {
        int e0 = warp_m * 64 + mt * 16 + group;
        int e1 = e0 + 8;
#pragma unroll
        for (int nt = 0; nt < 4; nt++) {
            int jb = warp_n * 32 + nt * 8 + tig * 2;
#pragma unroll
            for (int tile = 0; tile < 2; tile++) {
                int j = jb + tile * 128;
                if (j < 196) {
                    float a0v = tile ? acc1[mt][nt][0] : acc0[mt][nt][0];
                    float a1v = tile ? acc1[mt][nt][1] : acc0[mt][nt][1];
                    float a2v = tile ? acc1[mt][nt][2] : acc0[mt][nt][2];
                    float a3v = tile ? acc1[mt][nt][3] : acc0[mt][nt][3];
                    float v00 = fmaxf(a0v + vlbase[(size_t)e0 * NPIX + j],     0.f);
                    float v01 = fmaxf(a1v + vlbase[(size_t)e0 * NPIX + j + 1], 0.f);
                    float v10 = fmaxf(a2v + vlbase[(size_t)e1 * NPIX + j],     0.f);
                    float v11 = fmaxf(a3v + vlbase[(size_t)e1 * NPIX + j + 1], 0.f);
                    size_t r00 = ((size_t)(b * 196 + j))     * 1024 + o * 128 + e0;
                    size_t r01 = ((size_t)(b * 196 + j + 1)) * 1024 + o * 128 + e0;
                    g_pt[r00]     = __float2half(v00);
                    g_pt[r01]     = __float2half(v01);
                    g_pt[r00 + 8] = __float2half(v10);
                    g_pt[r01 + 8] = __float2half(v11);
                }
            }
        }
    }
}

// ------------------------------------------------------------------
// Depthwise 3x3 conv: reads single fp16 V export.
__global__ void __launch_bounds__(256) dwconv_kernel(
    const float* __restrict__ wvl, const float* __restrict__ bvl,
    const float* __restrict__ bn)
{
    int c0 = blockIdx.x * 8, b = blockIdx.y;
    __shared__ float p[8 * 256];
    __shared__ float wsh[72];
    __shared__ float cs[8], ct[8];
    int tid = threadIdx.x;
    const __half* vhi = g_vhi + ((size_t)b * 1024 + c0) * KPAD;

    for (int i = tid; i < 2048; i += 256) p[i] = 0.f;
    if (tid < 72) wsh[tid] = wvl[c0 * 9 + tid];
    if (tid < 8) {
        int c = c0 + tid;
        float s = bn[c] * rsqrtf(bn[3072 + c] + EPSF);
        cs[tid] = s;
        ct[tid] = (bvl[c] - bn[2048 + c]) * s + bn[1024 + c];
    }
    __syncthreads();

    for (int i = tid; i < 392; i += 256) {
        int c = i / 49, q = i - c * 49;
        int pix = q * 4;
        uint2 vh = *(const uint2*)(vhi + (size_t)c * KPAD + pix);
        const __half2* hp = (const __half2*)&vh;
        float2 h0 = __half22float2(hp[0]), h1 = __half22float2(hp[1]);
        float vals[4] = { h0.x, h0.y, h1.x, h1.y };
        int y = pix / 14, x = pix - y * 14;
#pragma unroll
        for (int e = 0; e < 4; e++) {
            p[c * 256 + (y + 1) * 16 + (x + 1)] = vals[e];
            if (++x == 14) { x = 0; ++y; }
        }
    }
    __syncthreads();

    int w = tid >> 5, lane = tid & 31;
    if (lane < 28) {
        const float* pc = p + w * 256;
        float w00 = wsh[w * 9 + 0], w01 = wsh[w * 9 + 1], w02 = wsh[w * 9 + 2];
        float w10 = wsh[w * 9 + 3], w11 = wsh[w * 9 + 4], w12 = wsh[w * 9 + 5];
        float w20 = wsh[w * 9 + 6], w21 = wsh[w * 9 + 7], w22 = wsh[w * 9 + 8];
        float s = cs[w], t = ct[w];
        float* dst = g_vloc + (size_t)b * (DHC * NPIX) + (size_t)(c0 + w) * NPIX;
        int xr = lane >= 14;
        int x = lane - xr * 14;
#pragma unroll
        for (int it = 0; it < 7; it++) {
            int y = it * 2 + xr;
            const float* q = pc + y * 16 + x;
            float acc = w00 * q[0]  + w01 * q[1]  + w02 * q[2]
                      + w10 * q[16] + w11 * q[17] + w12 * q[18]
                      + w20 * q[32] + w21 * q[33] + w22 * q[34];
            dst[y * 14 + x] = acc * s + t;
        }
    }
}

// ------------------------------------------------------------------
// Attention core: paired-m TH1 / softmax / TH2 + single-fp16 P export.
#define ATTN_SMEM_FLOATS (21952 + 144)

__global__ void __launch_bounds__(256, 2) attn_kernel(
    const float* __restrict__ th1w, const float* __restrict__ th1b,
    const float* __restrict__ th2w, const float* __restrict__ th2b)
{
    extern __shared__ float sm[];
    float* L  = sm;
    float* th = sm + 21952;

    int tid = threadIdx.x;
    int b = blockIdx.y;
    int n0 = blockIdx.x * 14;

    if (tid < 64)       th[tid] = th1w[tid];
    else if (tid < 72)  th[tid] = th1b[tid - 64];
    else if (tid < 136) th[tid] = th2w[tid - 72];
    else if (tid < 144) th[tid] = th2b[tid - 136];
    __syncthreads();

    const float* lgbase = g_logits + (size_t)(b * 8) * 196 * 196;
    for (int idx = tid; idx < 1372; idx += 256) {
        int n_ = idx / 98, m = (idx - n_ * 98) * 2;
        size_t rowoff = (size_t)(n0 + n_) * 196 + m;
        float2 v[8];
#pragma unroll
        for (int hh = 0; hh < 8; hh++)
            v[hh] = *(const float2*)(lgbase + (size_t)hh * 196 * 196 + rowoff);
#pragma unroll
        for (int oo = 0; oo < 8; oo++) {
            float s0 = th[64 + oo], s1 = th[64 + oo];
#pragma unroll
            for (int hh = 0; hh < 8; hh++) {
                float w = th[oo * 8 + hh];
                s0 = fmaf(w, v[hh].x, s0);
                s1 = fmaf(w, v[hh].y, s1);
            }
            *(float2*)(L + (oo * 14 + n_) * 196 + m) = make_float2(s0, s1);
        }
    }
    __syncthreads();

    {
        int w = tid >> 5, lane = tid & 31;
        for (int r = 0; r < 14; r++) {
            float* row = L + (w * 14 + r) * 196;
            float mx = -1e30f;
            for (int m = lane; m < 196; m += 32) mx = fmaxf(mx, row[m]);
#pragma unroll
            for (int off = 16; off > 0; off >>= 1)
                mx = fmaxf(mx, __shfl_xor_sync(0xffffffffu, mx, off));
            float sum = 0.f;
            for (int m = lane; m < 196; m += 32) {
                float e = __expf(row[m] - mx);
                row[m] = e; sum += e;
            }
#pragma unroll
            for (int off = 16; off > 0; off >>= 1)
                sum += __shfl_xor_sync(0xffffffffu, sum, off);
            float inv = 1.f / sum;
            for (int m = lane; m < 196; m += 32) row[m] *= inv;
        }
    }
    __syncthreads();

    for (int idx = tid; idx < 1372; idx += 256) {
        int n_ = idx / 98, m = (idx - n_ * 98) * 2;
        float2 v[8];
#pragma unroll
        for (int hh = 0; hh < 8; hh++)
            v[hh] = *(const float2*)(L + (hh * 14 + n_) * 196 + m);
        size_t rbase = (size_t)(b * 8) * 196 + n0 + n_;
#pragma unroll
        for (int oo = 0; oo < 8; oo++) {
            float s0 = th[136 + oo], s1 = th[136 + oo];
#pragma unroll
            for (int hh = 0; hh < 8; hh++) {
                float w = th[72 + oo * 8 + hh];
                s0 = fmaf(w, v[hh].x, s0);
                s1 = fmaf(w, v[hh].y, s1);
            }
            size_t row = rbase + (size_t)oo * 196;
            *(__half2*)(g_pf + row * KPAD + m) = __floats2half2_rn(s0, s1);
        }
    }
}

// ------------------------------------------------------------------
extern "C" void kernel_launch(void* const* d_in, const int* in_sizes, int n_in,
                              void* d_out, int out_size)
{
    const float* x    = (const float*)d_in[0];
    const float* wq   = (const float*)d_in[1];
    const float* bq   = (const float*)d_in[2];
    const float* bnq  = (const float*)d_in[3];
    const float* wk   = (const float*)d_in[4];
    const float* bk   = (const float*)d_in[5];
    const float* bnk  = (const float*)d_in[6];
    const float* wv   = (const float*)d_in[7];
    const float* bv   = (const float*)d_in[8];
    const float* bnv  = (const float*)d_in[9];
    const float* wvl  = (const float*)d_in[10];
    const float* bvl  = (const float*)d_in[11];
    const float* bnvl = (const float*)d_in[12];
    const float* th1w = (const float*)d_in[13];
    const float* th1b = (const float*)d_in[14];
    const float* th2w = (const float*)d_in[15];
    const float* th2b = (const float*)d_in[16];
    const float* wp   = (const float*)d_in[17];
    const float* bp   = (const float*)d_in[18];
    const float* bnp  = (const float*)d_in[19];
    const float* ab   = (const float*)d_in[20];
    const int*   bidx = (const int*)d_in[21];
    float* out = (float*)d_out;

    const int attn_smem = ATTN_SMEM_FLOATS * (int)sizeof(float);
    cudaFuncSetAttribute(attn_kernel,
                         cudaFuncAttributeMaxDynamicSharedMemorySize, attn_smem);
    cudaFuncSetAttribute(gemm_mma_kernel,
                         cudaFuncAttributeMaxDynamicSharedMemorySize, GEMM_SMEM_BYTES);
    cudaFuncSetAttribute(av_mma_kernel,
                         cudaFuncAttributeMaxDynamicSharedMemorySize, AV_SMEM_BYTES);
    cudaFuncSetAttribute(qk_mma_kernel,
                         cudaFuncAttributeMaxDynamicSharedMemorySize, QK_SMEM_BYTES);

    __half *wqkv_hi, *wqkv_lo, *xt, *wp_hi, *wp_lo, *pt;
    __nv_bfloat16 *qkh_hi, *qkh_lo;
    float *sv, *tv;
    cudaGetSymbolAddress((void**)&wqkv_hi, g_wqkv_hi);
    cudaGetSymbolAddress((void**)&wqkv_lo, g_wqkv_lo);
    cudaGetSymbolAddress((void**)&xt, g_xt);
    cudaGetSymbolAddress((void**)&wp_hi, g_wp_hi);
    cudaGetSymbolAddress((void**)&wp_lo, g_wp_lo);
    cudaGetSymbolAddress((void**)&pt, g_pt);
    cudaGetSymbolAddress((void**)&qkh_hi, g_qkh_hi);
    cudaGetSymbolAddress((void**)&qkh_lo, g_qkh_lo);
    cudaGetSymbolAddress((void**)&sv, g_s);
    cudaGetSymbolAddress((void**)&tv, g_t);

    // streams/events created once, outside any capture.
    static cudaStream_t s2 = nullptr;
    static cudaEvent_t evA, evB, evC, evD;
    if (s2 == nullptr) {
        cudaStreamCreateWithFlags(&s2, cudaStreamNonBlocking);
        cudaEventCreateWithFlags(&evA, cudaEventDisableTiming);
        cudaEventCreateWithFlags(&evB, cudaEventDisableTiming);
        cudaEventCreateWithFlags(&evC, cudaEventDisableTiming);
        cudaEventCreateWithFlags(&evD, cudaEventDisableTiming);
    }

    // fork: xt_cvt on s2 || prep1 on main
    cudaEventRecord(evA, 0);
    cudaStreamWaitEvent(s2, evA, 0);
    xt_cvt_kernel<<<dim3(7, 12, 64), 256, 0, s2>>>(x);
    prep_kernel<<<1152, 256>>>(wq, wk, wv, bq, bk, bv, bp, bnq, bnk, bnv, bnp);
    cudaEventRecord(evB, s2);
    cudaStreamWaitEvent(0, evB, 0);

    // s2: prep2 (wp split + pad zeroing) overlaps the qkv GEMM on main
    prep2_kernel<<<1152, 256, 0, s2>>>(wp);

    // qkv GEMM (fp16 2-pass): exports q/k (g_qkh) and V (g_vhi single fp16)
    gemm_mma_kernel<<<dim3(98, 12), 256, GEMM_SMEM_BYTES>>>(
        wqkv_hi, wqkv_lo, xt, 384, sv, tv, nullptr, 1536, qkh_hi, qkh_lo);

    // fork: dwconv on s2 || (qk -> attn) on main
    cudaEventRecord(evC, 0);
    cudaStreamWaitEvent(s2, evC, 0);
    dwconv_kernel<<<dim3(128, 64), 256, 0, s2>>>(wvl, bvl, bnvl);
    qk_mma_kernel<<<dim3(2, 2, 512), 256, QK_SMEM_BYTES>>>(ab, bidx);
    attn_kernel<<<dim3(14, 64), 256, attn_smem>>>(th1w, th1b, th2w, th2b);
    cudaEventRecord(evD, s2);
    cudaStreamWaitEvent(0, evD, 0);

    // AV (fp16 1-pass; epilogue writes fp16 g_pt), then proj GEMM (fp16 2-pass)
    av_mma_kernel<<<512, 256, AV_SMEM_BYTES>>>();
    gemm_mma_kernel<<<dim3(98, 3), 256, GEMM_SMEM_BYTES>>>(
        wp_hi, wp_lo, pt, 1024, sv + 1536, tv + 1536, out, 384,
        nullptr, nullptr);
}